// round 11
// baseline (speedup 1.0000x reference)
#include <cuda_runtime.h>
#include <cuda_bf16.h>
#include <math.h>
#include <stdint.h>

// ---------------- problem constants ----------------
#define T_TOK   2048
#define D_MODEL 1280
#define H_HEADS 16
#define HD      80
#define HALF    40
#define FF_DIM  3420
#define FF_PAD  3456
#define FF2     (2 * FF_PAD)          // 6912 fused gate|up
#define DEPTH   4
#define OUT_DIM 3584
#define PATCH_IN 1176
#define PATCH_KP 1216
#define WIN     64
#define NWIN    (T_TOK / WIN)
#define EPS_RMS 1e-6f
#define ATT_SCALE 0.1118033988749895f

typedef __nv_bfloat16 bf16;

// ---------------- helpers ----------------
__device__ __forceinline__ uint32_t smem_u32(const void* p) {
    uint32_t a;
    asm("{ .reg .u64 t; cvta.to.shared.u64 t, %1; cvt.u32.u64 %0, t; }" : "=r"(a) : "l"(p));
    return a;
}
__device__ __forceinline__ void cp_async16(uint32_t s, const void* g) {
    asm volatile("cp.async.cg.shared.global [%0], [%1], 16;" :: "r"(s), "l"(g));
}
#define CP_COMMIT() asm volatile("cp.async.commit_group;" ::: "memory")
#define CP_WAIT(n)  asm volatile("cp.async.wait_group %0;" :: "n"(n) : "memory")

__device__ __forceinline__ void ldm_x4(uint32_t& r0, uint32_t& r1, uint32_t& r2,
                                       uint32_t& r3, uint32_t addr) {
    asm volatile("ldmatrix.sync.aligned.m8n8.x4.shared.b16 {%0,%1,%2,%3}, [%4];"
                 : "=r"(r0), "=r"(r1), "=r"(r2), "=r"(r3) : "r"(addr));
}
__device__ __forceinline__ void mma16816(float* d, const uint32_t* a,
                                         uint32_t b0, uint32_t b1) {
    asm volatile("mma.sync.aligned.m16n8k16.row.col.f32.bf16.bf16.f32 "
                 "{%0,%1,%2,%3}, {%4,%5,%6,%7}, {%8,%9}, {%0,%1,%2,%3};"
                 : "+f"(d[0]), "+f"(d[1]), "+f"(d[2]), "+f"(d[3])
                 : "r"(a[0]), "r"(a[1]), "r"(a[2]), "r"(a[3]), "r"(b0), "r"(b1));
}
// swizzled smem byte offset: 64B rows, 16B segs, XOR key (row>>1)&3 (bank-conflict-free)
__device__ __forceinline__ uint32_t swz(int row, int seg) {
    return (uint32_t)(row * 64 + ((seg ^ ((row >> 1) & 3)) << 4));
}

// ---------------- scratch ----------------
__device__ float g_h  [T_TOK * D_MODEL];
__device__ float g_gu [(size_t)T_TOK * FF2];
__device__ float g_gub[DEPTH * FF2];
__device__ float g_part[(size_t)8 * 512 * 5120];   // split-K partials
__device__ bf16  g_xh [T_TOK * PATCH_KP],       g_xl [T_TOK * PATCH_KP];
__device__ bf16  g_nh [T_TOK * D_MODEL],        g_nl [T_TOK * D_MODEL];
__device__ bf16  g_ath[T_TOK * D_MODEL],        g_atl[T_TOK * D_MODEL];
__device__ bf16  g_uph[(size_t)T_TOK * FF_PAD], g_upl[(size_t)T_TOK * FF_PAD];
__device__ bf16  g_f1h[512 * 4 * D_MODEL],      g_f1l[512 * 4 * D_MODEL];
// transposed/split weights [N, Kp]
__device__ bf16 g_patchTh[1280 * PATCH_KP],              g_patchTl[1280 * PATCH_KP];
__device__ bf16 g_qkvTh [DEPTH * 3840 * 1280],           g_qkvTl [DEPTH * 3840 * 1280];
__device__ bf16 g_projTh[DEPTH * 1280 * 1280],           g_projTl[DEPTH * 1280 * 1280];
__device__ bf16 g_guTh  [(size_t)DEPTH * FF2 * 1280],    g_guTl  [(size_t)DEPTH * FF2 * 1280];
__device__ bf16 g_downTh[(size_t)DEPTH * 1280 * FF_PAD], g_downTl[(size_t)DEPTH * 1280 * FF_PAD];
__device__ bf16 g_fc1Th [5120 * 5120],                   g_fc1Tl [5120 * 5120];
__device__ bf16 g_fc2Th [3584 * 5120],                   g_fc2Tl [3584 * 5120];

// ---------------- activation split ----------------
__global__ void conv_act(const float* __restrict__ X, bf16* __restrict__ Xh,
                         bf16* __restrict__ Xl, int M, int K, int Kp) {
    int idx = blockIdx.x * 256 + threadIdx.x;
    if (idx >= M * Kp) return;
    int m = idx / Kp, k = idx - m * Kp;
    float v = (k < K) ? X[(size_t)m * K + k] : 0.f;
    bf16 h = __float2bfloat16(v);
    Xh[idx] = h;
    Xl[idx] = __float2bfloat16(v - __bfloat162float(h));
}

// ---------------- concat bias builder ----------------
__global__ void build_gub(const float* __restrict__ gb, const float* __restrict__ ub) {
    int idx = blockIdx.x * 256 + threadIdx.x;
    if (idx >= DEPTH * FF2) return;
    const int l = idx / FF2, c = idx - l * FF2;
    float v = 0.f;
    if (c < FF_DIM)                              v = gb[l * FF_DIM + c];
    else if (c >= FF_PAD && c < FF_PAD + FF_DIM) v = ub[l * FF_DIM + (c - FF_PAD)];
    g_gub[idx] = v;
}

// ---------------- batched weight transpose+split ----------------
#define NSEG 23
struct Seg { const float* s; bf16* dh; bf16* dl; int K, N, Kp, tile0, tilesX; };
struct ConvTable { Seg seg[NSEG]; };

__global__ void conv_all(ConvTable tb) {
    __shared__ float t[32][33];
    const int tile = blockIdx.x;
    int si = 0;
#pragma unroll
    for (int i = 1; i < NSEG; i++) si += (tb.seg[i].tile0 <= tile);
    const Seg sg = tb.seg[si];
    const int lt = tile - sg.tile0;
    const int kb = (lt % sg.tilesX) * 32;
    const int nb = (lt / sg.tilesX) * 32;
#pragma unroll
    for (int j = 0; j < 32; j += 8) {
        int k = kb + threadIdx.y + j, n = nb + threadIdx.x;
        t[threadIdx.y + j][threadIdx.x] =
            (k < sg.K && n < sg.N) ? sg.s[(size_t)k * sg.N + n] : 0.f;
    }
    __syncthreads();
#pragma unroll
    for (int j = 0; j < 32; j += 8) {
        int n = nb + threadIdx.y + j, k = kb + threadIdx.x;
        if (k < sg.Kp) {
            float v = t[threadIdx.x][threadIdx.y + j];
            bf16 h = __float2bfloat16(v);
            sg.dh[(size_t)n * sg.Kp + k] = h;
            sg.dl[(size_t)n * sg.Kp + k] = __float2bfloat16(v - __bfloat162float(h));
        }
    }
}

// ---------------- GEMM: fused-pass mainloop ----------------
// Each k32 chunk stage holds Ah|Al|Bh|Bl (4 x 128 rows x 64B = 32 KB).
// computeChunk does all 3 split products from co-resident tiles.
#define NSTAGE 6
#define STAGE_BYTES (4 * 128 * 64)            // 32768
#define GEMM_SMEM (NSTAGE * STAGE_BYTES)      // 196608 -> occ 1

#define GEMM_MAINLOOP(C0, C1)                                                      \
    loadChunk(C0 + 0, 0); loadChunk(C0 + 1, 1);                                    \
    loadChunk(C0 + 2, 2); loadChunk(C0 + 3, 3);                                    \
    for (int c = C0; c < C1; c += 2) {                                             \
        if (c + 2 < C1) { CP_WAIT(2); } else { CP_WAIT(0); }                       \
        __syncthreads();                                                           \
        if (c + 4 < C1) loadChunk(c + 4, (c + 4 - C0) % NSTAGE);                   \
        if (c + 5 < C1) loadChunk(c + 5, (c + 5 - C0) % NSTAGE);                   \
        computeChunk((c - C0) % NSTAGE);                                           \
        computeChunk((c + 1 - C0) % NSTAGE);                                       \
    }

#define GEMM_BODY_COMMON                                                           \
    const int kc = Kp >> 5;                                                        \
    const size_t rowB = (size_t)Kp * 2;                                            \
    const int ld_r = tid >> 2;                                                     \
    const int ld_s = tid & 3;                                                      \
    auto loadChunk = [&](int c, int buf) {                                         \
        const size_t kk = (size_t)c * 64;                                          \
        const char* pAh = (const char*)Ah + (size_t)row0 * rowB + kk;              \
        const char* pAl = (const char*)Al + (size_t)row0 * rowB + kk;              \
        const char* pBh = (const char*)Bh + (size_t)col0 * rowB + kk;              \
        const char* pBl = (const char*)Bl + (size_t)col0 * rowB + kk;              \
        const uint32_t sAh = sbase + buf * STAGE_BYTES;                            \
        const uint32_t sAl = sAh + 8192;                                           \
        const uint32_t sBh = sAh + 16384;                                          \
        const uint32_t sBl = sAh + 24576;                                          \
        _Pragma("unroll")                                                          \
        for (int i = 0; i < 2; i++) {                                              \
            const int r = ld_r + i * 64;                                           \
            const size_t go = (size_t)r * rowB + ld_s * 16;                        \
            const uint32_t so = swz(r, ld_s);                                      \
            cp_async16(sAh + so, pAh + go);                                        \
            cp_async16(sAl + so, pAl + go);                                        \
            cp_async16(sBh + so, pBh + go);                                        \
            cp_async16(sBl + so, pBl + go);                                        \
        }                                                                          \
        CP_COMMIT();                                                               \
    };                                                                             \
    float acc[4][4][4];                                                            \
    _Pragma("unroll")                                                              \
    for (int i = 0; i < 4; i++)                                                    \
        _Pragma("unroll")                                                          \
        for (int j = 0; j < 4; j++)                                                \
            _Pragma("unroll")                                                      \
            for (int q = 0; q < 4; q++) acc[i][j][q] = 0.f;                        \
    const int a_row = warp_m * 64 + (lane & 15);                                   \
    const int a_seg = (lane >> 4);                                                 \
    const int b_row = warp_n * 32 + (lane & 7) + ((lane >> 4) << 3);               \
    const int b_seg = (lane >> 3) & 1;                                             \
    auto computeChunk = [&](int buf) {                                             \
        const uint32_t sAh = sbase + buf * STAGE_BYTES;                            \
        const uint32_t sAl = sAh + 8192;                                           \
        const uint32_t sBh = sAh + 16384;                                          \
        const uint32_t sBl = sAh + 24576;                                          \
        _Pragma("unroll")                                                          \
        for (int s = 0; s < 2; s++) {                                              \
            uint32_t ah[4][4], bh[2][4], bl[2][4], al[4][4];                       \
            _Pragma("unroll")                                                      \
            for (int mi = 0; mi < 4; mi++)                                         \
                ldm_x4(ah[mi][0], ah[mi][1], ah[mi][2], ah[mi][3],                 \
                       sAh + swz(a_row + mi * 16, s * 2 + a_seg));                 \
            _Pragma("unroll")                                                      \
            for (int j = 0; j < 2; j++)                                            \
                ldm_x4(bh[j][0], bh[j][1], bh[j][2], bh[j][3],                     \
                       sBh + swz(b_row + j * 16, s * 2 + b_seg));                  \
            _Pragma("unroll")                                                      \
            for (int mi = 0; mi < 4; mi++)                                         \
                _Pragma("unroll")                                                  \
                for (int ni = 0; ni < 4; ni++)                                     \
                    mma16816(acc[mi][ni], ah[mi],                                  \
                             bh[ni >> 1][(ni & 1) * 2], bh[ni >> 1][(ni & 1) * 2 + 1]); \
            _Pragma("unroll")                                                      \
            for (int j = 0; j < 2; j++)                                            \
                ldm_x4(bl[j][0], bl[j][1], bl[j][2], bl[j][3],                     \
                       sBl + swz(b_row + j * 16, s * 2 + b_seg));                  \
            _Pragma("unroll")                                                      \
            for (int mi = 0; mi < 4; mi++)                                         \
                _Pragma("unroll")                                                  \
                for (int ni = 0; ni < 4; ni++)                                     \
                    mma16816(acc[mi][ni], ah[mi],                                  \
                             bl[ni >> 1][(ni & 1) * 2], bl[ni >> 1][(ni & 1) * 2 + 1]); \
            _Pragma("unroll")                                                      \
            for (int mi = 0; mi < 4; mi++)                                         \
                ldm_x4(al[mi][0], al[mi][1], al[mi][2], al[mi][3],                 \
                       sAl + swz(a_row + mi * 16, s * 2 + a_seg));                 \
            _Pragma("unroll")                                                      \
            for (int mi = 0; mi < 4; mi++)                                         \
                _Pragma("unroll")                                                  \
                for (int ni = 0; ni < 4; ni++)                                     \
                    mma16816(acc[mi][ni], al[mi],                                  \
                             bh[ni >> 1][(ni & 1) * 2], bh[ni >> 1][(ni & 1) * 2 + 1]); \
        }                                                                          \
    };

// ---- full GEMM with fused bias (gu, fc2; N multiple of 128) ----
__global__ __launch_bounds__(256, 1)
void gemm_bias(const bf16* __restrict__ Ah, const bf16* __restrict__ Al,
               const bf16* __restrict__ Bh, const bf16* __restrict__ Bl,
               const float* __restrict__ bias, float* __restrict__ C,
               int Kp, int N)
{
    extern __shared__ __align__(128) char smem[];
    const uint32_t sbase = smem_u32(smem);
    const int tid = threadIdx.x, lane = tid & 31, wid = tid >> 5;
    const int warp_m = wid >> 2, warp_n = wid & 3;
    const int row0 = blockIdx.x * 128, col0 = blockIdx.y * 128;

    GEMM_BODY_COMMON

    GEMM_MAINLOOP(0, kc)

    const int g = lane >> 2, tig = lane & 3;
#pragma unroll
    for (int mi = 0; mi < 4; mi++)
#pragma unroll
        for (int half = 0; half < 2; half++) {
            const int r = row0 + warp_m * 64 + mi * 16 + g + half * 8;
#pragma unroll
            for (int ni = 0; ni < 4; ni++) {
                const int col = col0 + warp_n * 32 + ni * 8 + tig * 2;
                const float2 bb = *(const float2*)(bias + col);
                *(float2*)(C + (size_t)r * N + col) =
                    make_float2(acc[mi][ni][half * 2 + 0] + bb.x,
                                acc[mi][ni][half * 2 + 1] + bb.y);
            }
        }
}

// ---- split-K GEMM: writes raw partials (grid.z = split index) ----
__global__ __launch_bounds__(256, 1)
void gemm_part(const bf16* __restrict__ Ah, const bf16* __restrict__ Al,
               const bf16* __restrict__ Bh, const bf16* __restrict__ Bl,
               float* __restrict__ part, size_t pstride,
               int Kp, int N)
{
    extern __shared__ __align__(128) char smem[];
    const uint32_t sbase = smem_u32(smem);
    const int tid = threadIdx.x, lane = tid & 31, wid = tid >> 5;
    const int warp_m = wid >> 2, warp_n = wid & 3;
    const int row0 = blockIdx.x * 128, col0 = blockIdx.y * 128;
    const int S = gridDim.z, sidx = blockIdx.z;

    GEMM_BODY_COMMON

    const int npair = kc >> 1;
    const int c0 = 2 * ((sidx * npair) / S);
    const int c1 = 2 * (((sidx + 1) * npair) / S);

    GEMM_MAINLOOP(c0, c1)

    float* P = part + (size_t)sidx * pstride;
    const int g = lane >> 2, tig = lane & 3;
#pragma unroll
    for (int mi = 0; mi < 4; mi++)
#pragma unroll
        for (int half = 0; half < 2; half++) {
            const int r = row0 + warp_m * 64 + mi * 16 + g + half * 8;
#pragma unroll
            for (int ni = 0; ni < 4; ni++) {
                const int col = col0 + warp_n * 32 + ni * 8 + tig * 2;
                *(float2*)(P + (size_t)r * N + col) =
                    make_float2(acc[mi][ni][half * 2 + 0], acc[mi][ni][half * 2 + 1]);
            }
        }
}

// ---------------- fused split-K reduce (+bias,+residual) + rmsnorm -> bf16 hi/lo ----------------
template <bool RES>
__global__ void reduce_rms(const float* __restrict__ part, size_t ps, int S,
                           const float* __restrict__ bias, const float* __restrict__ scale,
                           float* __restrict__ h, bf16* __restrict__ yh, bf16* __restrict__ yl)
{
    const int row = blockIdx.x;
    const size_t rb = (size_t)row * D_MODEL;
    float v[5];
    float sumsq = 0.f;
#pragma unroll
    for (int j = 0; j < 5; j++) {
        const int i = threadIdx.x + j * 256;
        float val = part[rb + i];
        for (int s = 1; s < S; s++) val += part[(size_t)s * ps + rb + i];
        if (RES) val += bias[i] + h[rb + i];
        h[rb + i] = val;
        v[j] = val;
        sumsq += val * val;
    }
#pragma unroll
    for (int o = 16; o; o >>= 1) sumsq += __shfl_xor_sync(~0u, sumsq, o);
    __shared__ float red[8];
    const int warp = threadIdx.x >> 5, lane = threadIdx.x & 31;
    if (lane == 0) red[warp] = sumsq;
    __syncthreads();
    if (warp == 0) {
        float t = (lane < 8) ? red[lane] : 0.f;
#pragma unroll
        for (int o = 4; o; o >>= 1) t += __shfl_xor_sync(~0u, t, o);
        if (lane == 0) red[0] = t;
    }
    __syncthreads();
    const float rinv = rsqrtf(red[0] * (1.f / D_MODEL) + EPS_RMS);
#pragma unroll
    for (int j = 0; j < 5; j++) {
        const int i = threadIdx.x + j * 256;
        const float y = v[j] * scale[i] * rinv;
        const bf16 hh = __float2bfloat16(y);
        yh[rb + i] = hh;
        yl[rb + i] = __float2bfloat16(y - __bfloat162float(hh));
    }
}

// ---------------- fc1 reduce: +bias, gelu, pair split ----------------
__global__ void reduce_gelu_pair(const float* __restrict__ part, size_t ps, int S,
                                 const float* __restrict__ bias,
                                 bf16* __restrict__ oh, bf16* __restrict__ ol,
                                 int n4, int N) {
    int i = blockIdx.x * 256 + threadIdx.x;
    if (i >= n4) return;
    const size_t b = (size_t)i * 4;
    float4 a = *(const float4*)(part + b);
    for (int s = 1; s < S; s++) {
        const float4 p = *(const float4*)(part + (size_t)s * ps + b);
        a.x += p.x; a.y += p.y; a.z += p.z; a.w += p.w;
    }
    const float4 bb = *(const float4*)(bias + (int)(b % N));
    float v[4] = { a.x + bb.x, a.y + bb.y, a.z + bb.z, a.w + bb.w };
    bf16 hh[4], ll[4];
#pragma unroll
    for (int j = 0; j < 4; j++) {
        const float gv = 0.5f * v[j] * (1.f + erff(v[j] * 0.7071067811865475f));
        hh[j] = __float2bfloat16(gv);
        ll[j] = __float2bfloat16(gv - __bfloat162float(hh[j]));
    }
    *(__nv_bfloat162*)(oh + b)     = __nv_bfloat162(hh[0], hh[1]);
    *(__nv_bfloat162*)(oh + b + 2) = __nv_bfloat162(hh[2], hh[3]);
    *(__nv_bfloat162*)(ol + b)     = __nv_bfloat162(ll[0], ll[1]);
    *(__nv_bfloat162*)(ol + b + 2) = __nv_bfloat162(ll[2], ll[3]);
}

// ---------------- silu(gate)*up + bf16 hi/lo split ----------------
__global__ void silu_mul_quant(const float* __restrict__ GU,
                               bf16* __restrict__ Uh, bf16* __restrict__ Ul)
{
    const int row = blockIdx.x;
    const float* gr = GU + (size_t)row * FF2;
    bf16* uh = Uh + (size_t)row * FF_PAD;
    bf16* ul = Ul + (size_t)row * FF_PAD;
    for (int i = threadIdx.x; i < FF_PAD; i += 256) {
        float v = 0.f;
        if (i < FF_DIM) {
            const float gv = gr[i];
            v = (gv / (1.f + __expf(-gv))) * gr[FF_PAD + i];
        }
        const bf16 h = __float2bfloat16(v);
        uh[i] = h;
        ul[i] = __float2bfloat16(v - __bfloat162float(h));
    }
}

// ---------------- attention: fused qkv split-K(S=2) reduce + bias + RoPE ----------------
#define ATT_SMEM ((64 * 80 + 64 * 81 + 64 * 80 + 8 * 64) * 4)

__global__ void attn_kernel(const float* __restrict__ part, size_t ps,
                            const float* __restrict__ qkvb,
                            const float* __restrict__ rot,
                            bf16* __restrict__ oh, bf16* __restrict__ ol)
{
    extern __shared__ float sm[];
    float* qs = sm;
    float* ks = qs + 64 * 80;
    float* vs = ks + 64 * 81;
    float* pr = vs + 64 * 80;
    const int w = blockIdx.x, hh = blockIdx.y;
    const int tid = threadIdx.x, lane = tid & 31, warp = tid >> 5;
    const size_t base = (size_t)w * WIN * (3 * D_MODEL) + hh * HD;
    const int cb = hh * HD;

    for (int idx = tid; idx < WIN * HALF; idx += 256) {
        const int t = idx / HALF, d = idx % HALF;
        float s, c;
        sincosf(rot[(w * WIN + t) * HALF + d], &s, &c);
        const size_t g = base + (size_t)t * (3 * D_MODEL) + d;
        const float qre = part[g] + part[ps + g] + qkvb[cb + d];
        const float qim = part[g + HALF] + part[ps + g + HALF] + qkvb[cb + d + HALF];
        const float kre = part[g + D_MODEL] + part[ps + g + D_MODEL] + qkvb[cb + d + D_MODEL];
        const float kim = part[g + D_MODEL + HALF] + part[ps + g + D_MODEL + HALF]
                        + qkvb[cb + d + D_MODEL + HALF];
        qs[t * 80 + d]        = qre * c - qim * s;
        qs[t * 80 + d + HALF] = qre * s + qim * c;
        ks[t * 81 + d]        = kre * c - kim * s;
        ks[t * 81 + d + HALF] = kre * s + kim * c;
    }
    for (int idx = tid; idx < WIN * HD; idx += 256) {
        const int t = idx / HD, d = idx % HD;
        const size_t g = base + (size_t)t * (3 * D_MODEL) + 2 * D_MODEL + d;
        vs[t * 80 + d] = part[g] + part[ps + g] + qkvb[cb + d + 2 * D_MODEL];
    }
    __syncthreads();

    for (int row = warp; row < WIN; row += 8) {
        const float* qr = qs + row * 80;
        const float* k0 = ks + lane * 81;
        const float* k1 = ks + (lane + 32) * 81;
        float s0 = 0.f, s1 = 0.f;
#pragma unroll
        for (int d = 0; d < HD; d++) { const float q = qr[d]; s0 += q * k0[d]; s1 += q * k1[d]; }
        s0 *= ATT_SCALE; s1 *= ATT_SCALE;
        float mx = fmaxf(s0, s1);
#pragma unroll
        for (int o = 16; o; o >>= 1) mx = fmaxf(mx, __shfl_xor_sync(~0u, mx, o));
        const float e0 = __expf(s0 - mx), e1 = __expf(s1 - mx);
        float sum = e0 + e1;
#pragma unroll
        for (int o = 16; o; o >>= 1) sum += __shfl_xor_sync(~0u, sum, o);
        const float inv = 1.f / sum;
        pr[warp * 64 + lane] = e0 * inv;
        pr[warp * 64 + lane + 32] = e1 * inv;
        __syncwarp();
        float o0 = 0.f, o1 = 0.f, o2 = 0.f;
#pragma unroll 4
        for (int j = 0; j < WIN; j++) {
            const float p = pr[warp * 64 + j];
            const float* vr = vs + j * 80;
            o0 += p * vr[lane];
            o1 += p * vr[lane + 32];
            if (lane < 16) o2 += p * vr[lane + 64];
        }
        const size_t ob = (size_t)(w * WIN + row) * D_MODEL + hh * HD;
        bf16 h;
        h = __float2bfloat16(o0); oh[ob + lane] = h;
        ol[ob + lane] = __float2bfloat16(o0 - __bfloat162float(h));
        h = __float2bfloat16(o1); oh[ob + lane + 32] = h;
        ol[ob + lane + 32] = __float2bfloat16(o1 - __bfloat162float(h));
        if (lane < 16) {
            h = __float2bfloat16(o2); oh[ob + lane + 64] = h;
            ol[ob + lane + 64] = __float2bfloat16(o2 - __bfloat162float(h));
        }
        __syncwarp();
    }
}

// ---------------- host ----------------
extern "C" void kernel_launch(void* const* d_in, const int* in_sizes, int n_in,
                              void* d_out, int out_size)
{
    const float* x      = (const float*)d_in[0];
    const float* rot    = (const float*)d_in[1];
    const float* patchw = (const float*)d_in[3];
    const float* qkvw   = (const float*)d_in[4];
    const float* qkvb   = (const float*)d_in[5];
    const float* projw  = (const float*)d_in[6];
    const float* projb  = (const float*)d_in[7];
    const float* n1s    = (const float*)d_in[8];
    const float* n2s    = (const float*)d_in[9];
    const float* gw     = (const float*)d_in[10];
    const float* gb     = (const float*)d_in[11];
    const float* uw     = (const float*)d_in[12];
    const float* ub     = (const float*)d_in[13];
    const float* dw     = (const float*)d_in[14];
    const float* db     = (const float*)d_in[15];
    const float* lnq    = (const float*)d_in[16];
    const float* f1w    = (const float*)d_in[17];
    const float* f1b    = (const float*)d_in[18];
    const float* f2w    = (const float*)d_in[19];
    const float* f2b    = (const float*)d_in[20];
    float* out = (float*)d_out;

    float *h, *gu, *gub, *part;
    bf16 *xh, *xl, *nh, *nl, *ath, *atl, *uph, *upl, *f1h, *f1l;
    bf16 *patchTh, *patchTl, *qkvTh, *qkvTl, *projTh, *projTl;
    bf16 *guTh, *guTl, *downTh, *downTl, *fc1Th, *fc1Tl, *fc2Th, *fc2Tl;
#define GA(p, s) cudaGetSymbolAddress((void**)&p, s)
    GA(h, g_h); GA(gu, g_gu); GA(gub, g_gub); GA(part, g_part);
    GA(xh, g_xh); GA(xl, g_xl); GA(nh, g_nh); GA(nl, g_nl);
    GA(ath, g_ath); GA(atl, g_atl); GA(uph, g_uph); GA(upl, g_upl);
    GA(f1h, g_f1h); GA(f1l, g_f1l);
    GA(patchTh, g_patchTh); GA(patchTl, g_patchTl);
    GA(qkvTh, g_qkvTh); GA(qkvTl, g_qkvTl);
    GA(projTh, g_projTh); GA(projTl, g_projTl);
    GA(guTh, g_guTh); GA(guTl, g_guTl);
    GA(downTh, g_downTh); GA(downTl, g_downTl);
    GA(fc1Th, g_fc1Th); GA(fc1Tl, g_fc1Tl);
    GA(fc2Th, g_fc2Th); GA(fc2Tl, g_fc2Tl);
#undef GA

    cudaFuncSetAttribute(attn_kernel, cudaFuncAttributeMaxDynamicSharedMemorySize, ATT_SMEM);
    cudaFuncSetAttribute(gemm_bias, cudaFuncAttributeMaxDynamicSharedMemorySize, GEMM_SMEM);
    cudaFuncSetAttribute(gemm_part, cudaFuncAttributeMaxDynamicSharedMemorySize, GEMM_SMEM);

    // ---- setup: splits + weight conversion ----
    conv_act<<<(T_TOK * PATCH_KP + 255) / 256, 256>>>(x, xh, xl, T_TOK, PATCH_IN, PATCH_KP);
    build_gub<<<(DEPTH * FF2 + 255) / 256, 256>>>(gb, ub);
    {
        ConvTable tb;
        int tc = 0, si = 0;
        auto add = [&](const float* s, bf16* dh, bf16* dl, int K, int N, int Kp, int Np) {
            const int tx = (Kp + 31) / 32, ty = (Np + 31) / 32;
            tb.seg[si] = { s, dh, dl, K, N, Kp, tc, tx };
            tc += tx * ty; si++;
        };
        add(patchw, patchTh, patchTl, PATCH_IN, 1280, PATCH_KP, 1280);
        for (int l = 0; l < DEPTH; l++) {
            add(qkvw + (size_t)l * 1280 * 3840, qkvTh + (size_t)l * 3840 * 1280,
                qkvTl + (size_t)l * 3840 * 1280, 1280, 3840, 1280, 3840);
            add(projw + (size_t)l * 1280 * 1280, projTh + (size_t)l * 1280 * 1280,
                projTl + (size_t)l * 1280 * 1280, 1280, 1280, 1280, 1280);
            add(gw + (size_t)l * 1280 * FF_DIM, guTh + (size_t)l * FF2 * 1280,
                guTl + (size_t)l * FF2 * 1280, 1280, FF_DIM, 1280, FF_PAD);
            add(uw + (size_t)l * 1280 * FF_DIM,
                guTh + (size_t)l * FF2 * 1280 + (size_t)FF_PAD * 1280,
                guTl + (size_t)l * FF2 * 1280 + (size_t)FF_PAD * 1280,
                1280, FF_DIM, 1280, FF_PAD);
            add(dw + (size_t)l * FF_DIM * 1280, downTh + (size_t)l * 1280 * FF_PAD,
                downTl + (size_t)l * 1280 * FF_PAD, FF_DIM, 1280, FF_PAD, 1280);
        }
        add(f1w, fc1Th, fc1Tl, 5120, 5120, 5120, 5120);
        add(f2w, fc2Th, fc2Tl, 5120, 3584, 5120, 3584);
        conv_all<<<tc, dim3(32, 8)>>>(tb);
    }

    const size_t psD = (size_t)T_TOK * D_MODEL;
    const size_t psQ = (size_t)T_TOK * 3 * D_MODEL;
    const size_t psF = (size_t)512 * 5120;
    const int n4F = 512 * 5120 / 4;

    // ---- patch embed: split-K4 + fused reduce/rmsnorm(n1 layer0) ----
    gemm_part<<<dim3(16, 10, 4), 256, GEMM_SMEM>>>(
        xh, xl, patchTh, patchTl, part, psD, PATCH_KP, 1280);
    reduce_rms<false><<<T_TOK, 256>>>(part, psD, 4, nullptr, n1s, h, nh, nl);

    for (int l = 0; l < DEPTH; l++) {
        const size_t lD = (size_t)l * D_MODEL;
        // qkv: split-K2; reduction fused into attention
        gemm_part<<<dim3(16, 30, 2), 256, GEMM_SMEM>>>(
            nh, nl, qkvTh + (size_t)l * 3840 * 1280, qkvTl + (size_t)l * 3840 * 1280,
            part, psQ, 1280, 3840);
        attn_kernel<<<dim3(NWIN, H_HEADS), 256, ATT_SMEM>>>(
            part, psQ, qkvb + (size_t)l * 3840, rot, ath, atl);
        // proj: split-K4, then fused reduce+res+rmsnorm(n2)
        gemm_part<<<dim3(16, 10, 4), 256, GEMM_SMEM>>>(
            ath, atl, projTh + (size_t)l * 1280 * 1280, projTl + (size_t)l * 1280 * 1280,
            part, psD, 1280, 1280);
        reduce_rms<true><<<T_TOK, 256>>>(part, psD, 4, projb + lD, n2s + lD, h, nh, nl);
        // fused gate|up GEMM
        gemm_bias<<<dim3(16, FF2 / 128), 256, GEMM_SMEM>>>(
            nh, nl, guTh + (size_t)l * FF2 * 1280, guTl + (size_t)l * FF2 * 1280,
            gub + (size_t)l * FF2, gu, 1280, FF2);
        silu_mul_quant<<<T_TOK, 256>>>(gu, uph, upl);
        // down: split-K4, then fused reduce+res+rmsnorm(next n1 or lnq)
        gemm_part<<<dim3(16, 10, 4), 256, GEMM_SMEM>>>(
            uph, upl, downTh + (size_t)l * 1280 * FF_PAD, downTl + (size_t)l * 1280 * FF_PAD,
            part, psD, FF_PAD, 1280);
        const float* nexts = (l < DEPTH - 1) ? (n1s + (size_t)(l + 1) * D_MODEL) : lnq;
        reduce_rms<true><<<T_TOK, 256>>>(part, psD, 4, db + lD, nexts, h, nh, nl);
    }

    // ---- merger (nh/nl viewed as [512, 5120]) ----
    gemm_part<<<dim3(4, 40, 8), 256, GEMM_SMEM>>>(
        nh, nl, fc1Th, fc1Tl, part, psF, 5120, 5120);
    reduce_gelu_pair<<<(n4F + 255) / 256, 256>>>(part, psF, 8, f1b, f1h, f1l, n4F, 5120);
    gemm_bias<<<dim3(4, 28), 256, GEMM_SMEM>>>(
        f1h, f1l, fc2Th, fc2Tl, f2b, out, 5120, 3584);
}

// round 13
// speedup vs baseline: 1.4952x; 1.4952x over previous
#include <cuda_runtime.h>
#include <cuda_bf16.h>
#include <math.h>
#include <stdint.h>

// ---------------- problem constants ----------------
#define T_TOK   2048
#define D_MODEL 1280
#define H_HEADS 16
#define HD      80
#define HALF    40
#define FF_DIM  3420
#define FF_PAD  3456
#define FF2     (2 * FF_PAD)          // 6912 fused gate|up
#define DEPTH   4
#define OUT_DIM 3584
#define PATCH_IN 1176
#define PATCH_KP 1216
#define WIN     64
#define NWIN    (T_TOK / WIN)
#define EPS_RMS 1e-6f
#define ATT_SCALE 0.1118033988749895f

typedef __nv_bfloat16 bf16;

// ---------------- helpers ----------------
__device__ __forceinline__ uint32_t smem_u32(const void* p) {
    uint32_t a;
    asm("{ .reg .u64 t; cvta.to.shared.u64 t, %1; cvt.u32.u64 %0, t; }" : "=r"(a) : "l"(p));
    return a;
}
__device__ __forceinline__ void cp_async16(uint32_t s, const void* g) {
    asm volatile("cp.async.cg.shared.global [%0], [%1], 16;" :: "r"(s), "l"(g));
}
#define CP_COMMIT() asm volatile("cp.async.commit_group;" ::: "memory")
#define CP_WAIT(n)  asm volatile("cp.async.wait_group %0;" :: "n"(n) : "memory")

__device__ __forceinline__ void ldm_x4(uint32_t& r0, uint32_t& r1, uint32_t& r2,
                                       uint32_t& r3, uint32_t addr) {
    asm volatile("ldmatrix.sync.aligned.m8n8.x4.shared.b16 {%0,%1,%2,%3}, [%4];"
                 : "=r"(r0), "=r"(r1), "=r"(r2), "=r"(r3) : "r"(addr));
}
__device__ __forceinline__ void mma16816(float* d, const uint32_t* a,
                                         uint32_t b0, uint32_t b1) {
    asm volatile("mma.sync.aligned.m16n8k16.row.col.f32.bf16.bf16.f32 "
                 "{%0,%1,%2,%3}, {%4,%5,%6,%7}, {%8,%9}, {%0,%1,%2,%3};"
                 : "+f"(d[0]), "+f"(d[1]), "+f"(d[2]), "+f"(d[3])
                 : "r"(a[0]), "r"(a[1]), "r"(a[2]), "r"(a[3]), "r"(b0), "r"(b1));
}
// swizzled smem byte offset for 32B rows (two 16B segs), conflict-free for ldmatrix
__device__ __forceinline__ uint32_t swz16(int row, int seg) {
    return (uint32_t)(row * 32 + ((seg ^ ((row >> 2) & 1)) << 4));
}

// ---------------- scratch ----------------
__device__ float g_h  [T_TOK * D_MODEL];
__device__ float g_gu [(size_t)T_TOK * FF2];
__device__ float g_gub[DEPTH * FF2];
__device__ float g_part[(size_t)8 * 512 * 5120];   // split-K partials
__device__ bf16  g_xh [T_TOK * PATCH_KP],       g_xl [T_TOK * PATCH_KP];
__device__ bf16  g_nh [T_TOK * D_MODEL],        g_nl [T_TOK * D_MODEL];
__device__ bf16  g_ath[T_TOK * D_MODEL],        g_atl[T_TOK * D_MODEL];
__device__ bf16  g_uph[(size_t)T_TOK * FF_PAD], g_upl[(size_t)T_TOK * FF_PAD];
__device__ bf16  g_f1h[512 * 4 * D_MODEL],      g_f1l[512 * 4 * D_MODEL];
// transposed/split weights [N, Kp]
__device__ bf16 g_patchTh[1280 * PATCH_KP],              g_patchTl[1280 * PATCH_KP];
__device__ bf16 g_qkvTh [DEPTH * 3840 * 1280],           g_qkvTl [DEPTH * 3840 * 1280];
__device__ bf16 g_projTh[DEPTH * 1280 * 1280],           g_projTl[DEPTH * 1280 * 1280];
__device__ bf16 g_guTh  [(size_t)DEPTH * FF2 * 1280],    g_guTl  [(size_t)DEPTH * FF2 * 1280];
__device__ bf16 g_downTh[(size_t)DEPTH * 1280 * FF_PAD], g_downTl[(size_t)DEPTH * 1280 * FF_PAD];
__device__ bf16 g_fc1Th [5120 * 5120],                   g_fc1Tl [5120 * 5120];
__device__ bf16 g_fc2Th [3584 * 5120],                   g_fc2Tl [3584 * 5120];

// ---------------- activation split ----------------
__global__ void conv_act(const float* __restrict__ X, bf16* __restrict__ Xh,
                         bf16* __restrict__ Xl, int M, int K, int Kp) {
    int idx = blockIdx.x * 256 + threadIdx.x;
    if (idx >= M * Kp) return;
    int m = idx / Kp, k = idx - m * Kp;
    float v = (k < K) ? X[(size_t)m * K + k] : 0.f;
    bf16 h = __float2bfloat16(v);
    Xh[idx] = h;
    Xl[idx] = __float2bfloat16(v - __bfloat162float(h));
}

// ---------------- concat bias builder ----------------
__global__ void build_gub(const float* __restrict__ gb, const float* __restrict__ ub) {
    int idx = blockIdx.x * 256 + threadIdx.x;
    if (idx >= DEPTH * FF2) return;
    const int l = idx / FF2, c = idx - l * FF2;
    float v = 0.f;
    if (c < FF_DIM)                              v = gb[l * FF_DIM + c];
    else if (c >= FF_PAD && c < FF_PAD + FF_DIM) v = ub[l * FF_DIM + (c - FF_PAD)];
    g_gub[idx] = v;
}

// ---------------- batched weight transpose+split ----------------
#define NSEG 23
struct Seg { const float* s; bf16* dh; bf16* dl; int K, N, Kp, tile0, tilesX; };
struct ConvTable { Seg seg[NSEG]; };

__global__ void conv_all(ConvTable tb) {
    __shared__ float t[32][33];
    const int tile = blockIdx.x;
    int si = 0;
#pragma unroll
    for (int i = 1; i < NSEG; i++) si += (tb.seg[i].tile0 <= tile);
    const Seg sg = tb.seg[si];
    const int lt = tile - sg.tile0;
    const int kb = (lt % sg.tilesX) * 32;
    const int nb = (lt / sg.tilesX) * 32;
#pragma unroll
    for (int j = 0; j < 32; j += 8) {
        int k = kb + threadIdx.y + j, n = nb + threadIdx.x;
        t[threadIdx.y + j][threadIdx.x] =
            (k < sg.K && n < sg.N) ? sg.s[(size_t)k * sg.N + n] : 0.f;
    }
    __syncthreads();
#pragma unroll
    for (int j = 0; j < 32; j += 8) {
        int n = nb + threadIdx.y + j, k = kb + threadIdx.x;
        if (k < sg.Kp) {
            float v = t[threadIdx.x][threadIdx.y + j];
            bf16 h = __float2bfloat16(v);
            sg.dh[(size_t)n * sg.Kp + k] = h;
            sg.dl[(size_t)n * sg.Kp + k] = __float2bfloat16(v - __bfloat162float(h));
        }
    }
}

// ---------------- GEMM: fused-pass mainloop, k16 chunks, occ 2 ----------------
// Stage = Ah|Al|Bh|Bl, each 128 rows x 32B = 4 KB -> 16 KB/stage, 6 stages = 96 KB.
#define NSTAGE 6
#define STAGE_BYTES (4 * 128 * 32)            // 16384
#define GEMM_SMEM (NSTAGE * STAGE_BYTES)      // 98304 -> 2 CTAs/SM

#define GEMM_MAINLOOP(C0, C1)                                                      \
    loadChunk(C0 + 0, 0); loadChunk(C0 + 1, 1);                                    \
    loadChunk(C0 + 2, 2); loadChunk(C0 + 3, 3);                                    \
    for (int c = C0; c < C1; c += 2) {                                             \
        if (c + 2 < C1) { CP_WAIT(2); } else { CP_WAIT(0); }                       \
        __syncthreads();                                                           \
        if (c + 4 < C1) loadChunk(c + 4, (c + 4 - C0) % NSTAGE);                   \
        if (c + 5 < C1) loadChunk(c + 5, (c + 5 - C0) % NSTAGE);                   \
        computeChunk((c - C0) % NSTAGE);                                           \
        computeChunk((c + 1 - C0) % NSTAGE);                                       \
    }

#define GEMM_BODY_COMMON                                                           \
    const int kc = Kp >> 4;            /* k16 chunks */                            \
    const size_t rowB = (size_t)Kp * 2;                                            \
    const int ld_r = tid >> 1;         /* 0..127 */                                \
    const int ld_s = tid & 1;          /* 16B seg */                               \
    auto loadChunk = [&](int c, int buf) {                                         \
        const size_t kk = (size_t)c * 32;                                          \
        const size_t go = (size_t)ld_r * rowB + kk + ld_s * 16;                    \
        const uint32_t so = swz16(ld_r, ld_s);                                     \
        const uint32_t sAh = sbase + buf * STAGE_BYTES;                            \
        cp_async16(sAh + so,         (const char*)Ah + (size_t)row0 * rowB + go);  \
        cp_async16(sAh + 4096 + so,  (const char*)Al + (size_t)row0 * rowB + go);  \
        cp_async16(sAh + 8192 + so,  (const char*)Bh + (size_t)col0 * rowB + go);  \
        cp_async16(sAh + 12288 + so, (const char*)Bl + (size_t)col0 * rowB + go);  \
        CP_COMMIT();                                                               \
    };                                                                             \
    float acc[4][4][4];                                                            \
    _Pragma("unroll")                                                              \
    for (int i = 0; i < 4; i++)                                                    \
        _Pragma("unroll")                                                          \
        for (int j = 0; j < 4; j++)                                                \
            _Pragma("unroll")                                                      \
            for (int q = 0; q < 4; q++) acc[i][j][q] = 0.f;                        \
    const int a_row = warp_m * 64 + (lane & 15);                                   \
    const int a_seg = (lane >> 4);                                                 \
    const int b_row = warp_n * 32 + (lane & 7) + ((lane >> 4) << 3);               \
    const int b_seg = (lane >> 3) & 1;                                             \
    auto computeChunk = [&](int buf) {                                             \
        const uint32_t sAh = sbase + buf * STAGE_BYTES;                            \
        const uint32_t sAl = sAh + 4096;                                           \
        const uint32_t sBh = sAh + 8192;                                           \
        const uint32_t sBl = sAh + 12288;                                          \
        uint32_t a[4][4], b1[2][4], b2[2][4];                                      \
        _Pragma("unroll")                                                          \
        for (int mi = 0; mi < 4; mi++)                                             \
            ldm_x4(a[mi][0], a[mi][1], a[mi][2], a[mi][3],                         \
                   sAh + swz16(a_row + mi * 16, a_seg));                           \
        _Pragma("unroll")                                                          \
        for (int j = 0; j < 2; j++)                                                \
            ldm_x4(b1[j][0], b1[j][1], b1[j][2], b1[j][3],                         \
                   sBh + swz16(b_row + j * 16, b_seg));                            \
        _Pragma("unroll")                                                          \
        for (int mi = 0; mi < 4; mi++)                                             \
            _Pragma("unroll")                                                      \
            for (int ni = 0; ni < 4; ni++)                                         \
                mma16816(acc[mi][ni], a[mi],                                       \
                         b1[ni >> 1][(ni & 1) * 2], b1[ni >> 1][(ni & 1) * 2 + 1]);\
        _Pragma("unroll")                                                          \
        for (int j = 0; j < 2; j++)                                                \
            ldm_x4(b2[j][0], b2[j][1], b2[j][2], b2[j][3],                         \
                   sBl + swz16(b_row + j * 16, b_seg));                            \
        _Pragma("unroll")                                                          \
        for (int mi = 0; mi < 4; mi++)                                             \
            _Pragma("unroll")                                                      \
            for (int ni = 0; ni < 4; ni++)                                         \
                mma16816(acc[mi][ni], a[mi],                                       \
                         b2[ni >> 1][(ni & 1) * 2], b2[ni >> 1][(ni & 1) * 2 + 1]);\
        _Pragma("unroll")                                                          \
        for (int mi = 0; mi < 4; mi++)                                             \
            ldm_x4(a[mi][0], a[mi][1], a[mi][2], a[mi][3],                         \
                   sAl + swz16(a_row + mi * 16, a_seg));                           \
        _Pragma("unroll")                                                          \
        for (int mi = 0; mi < 4; mi++)                                             \
            _Pragma("unroll")                                                      \
            for (int ni = 0; ni < 4; ni++)                                         \
                mma16816(acc[mi][ni], a[mi],                                       \
                         b1[ni >> 1][(ni & 1) * 2], b1[ni >> 1][(ni & 1) * 2 + 1]);\
    };

// ---- full GEMM with fused bias (gu, fc2; N multiple of 128) ----
__global__ __launch_bounds__(256, 2)
void gemm_bias(const bf16* __restrict__ Ah, const bf16* __restrict__ Al,
               const bf16* __restrict__ Bh, const bf16* __restrict__ Bl,
               const float* __restrict__ bias, float* __restrict__ C,
               int Kp, int N)
{
    extern __shared__ __align__(128) char smem[];
    const uint32_t sbase = smem_u32(smem);
    const int tid = threadIdx.x, lane = tid & 31, wid = tid >> 5;
    const int warp_m = wid >> 2, warp_n = wid & 3;
    const int row0 = blockIdx.x * 128, col0 = blockIdx.y * 128;

    GEMM_BODY_COMMON

    GEMM_MAINLOOP(0, kc)

    const int g = lane >> 2, tig = lane & 3;
#pragma unroll
    for (int mi = 0; mi < 4; mi++)
#pragma unroll
        for (int half = 0; half < 2; half++) {
            const int r = row0 + warp_m * 64 + mi * 16 + g + half * 8;
#pragma unroll
            for (int ni = 0; ni < 4; ni++) {
                const int col = col0 + warp_n * 32 + ni * 8 + tig * 2;
                const float2 bb = *(const float2*)(bias + col);
                *(float2*)(C + (size_t)r * N + col) =
                    make_float2(acc[mi][ni][half * 2 + 0] + bb.x,
                                acc[mi][ni][half * 2 + 1] + bb.y);
            }
        }
}

// ---- split-K GEMM: writes raw partials (grid.z = split index) ----
__global__ __launch_bounds__(256, 2)
void gemm_part(const bf16* __restrict__ Ah, const bf16* __restrict__ Al,
               const bf16* __restrict__ Bh, const bf16* __restrict__ Bl,
               float* __restrict__ part, size_t pstride,
               int Kp, int N)
{
    extern __shared__ __align__(128) char smem[];
    const uint32_t sbase = smem_u32(smem);
    const int tid = threadIdx.x, lane = tid & 31, wid = tid >> 5;
    const int warp_m = wid >> 2, warp_n = wid & 3;
    const int row0 = blockIdx.x * 128, col0 = blockIdx.y * 128;
    const int S = gridDim.z, sidx = blockIdx.z;

    GEMM_BODY_COMMON

    const int npair = kc >> 1;
    const int c0 = 2 * ((sidx * npair) / S);
    const int c1 = 2 * (((sidx + 1) * npair) / S);

    GEMM_MAINLOOP(c0, c1)

    float* P = part + (size_t)sidx * pstride;
    const int g = lane >> 2, tig = lane & 3;
#pragma unroll
    for (int mi = 0; mi < 4; mi++)
#pragma unroll
        for (int half = 0; half < 2; half++) {
            const int r = row0 + warp_m * 64 + mi * 16 + g + half * 8;
#pragma unroll
            for (int ni = 0; ni < 4; ni++) {
                const int col = col0 + warp_n * 32 + ni * 8 + tig * 2;
                *(float2*)(P + (size_t)r * N + col) =
                    make_float2(acc[mi][ni][half * 2 + 0], acc[mi][ni][half * 2 + 1]);
            }
        }
}

// ---------------- fused split-K reduce (+bias,+residual) + rmsnorm -> bf16 hi/lo ----------------
template <bool RES>
__global__ void reduce_rms(const float* __restrict__ part, size_t ps, int S,
                           const float* __restrict__ bias, const float* __restrict__ scale,
                           float* __restrict__ h, bf16* __restrict__ yh, bf16* __restrict__ yl)
{
    const int row = blockIdx.x;
    const size_t rb = (size_t)row * D_MODEL;
    float v[5];
    float sumsq = 0.f;
#pragma unroll
    for (int j = 0; j < 5; j++) {
        const int i = threadIdx.x + j * 256;
        float val = part[rb + i];
        for (int s = 1; s < S; s++) val += part[(size_t)s * ps + rb + i];
        if (RES) val += bias[i] + h[rb + i];
        h[rb + i] = val;
        v[j] = val;
        sumsq += val * val;
    }
#pragma unroll
    for (int o = 16; o; o >>= 1) sumsq += __shfl_xor_sync(~0u, sumsq, o);
    __shared__ float red[8];
    const int warp = threadIdx.x >> 5, lane = threadIdx.x & 31;
    if (lane == 0) red[warp] = sumsq;
    __syncthreads();
    if (warp == 0) {
        float t = (lane < 8) ? red[lane] : 0.f;
#pragma unroll
        for (int o = 4; o; o >>= 1) t += __shfl_xor_sync(~0u, t, o);
        if (lane == 0) red[0] = t;
    }
    __syncthreads();
    const float rinv = rsqrtf(red[0] * (1.f / D_MODEL) + EPS_RMS);
#pragma unroll
    for (int j = 0; j < 5; j++) {
        const int i = threadIdx.x + j * 256;
        const float y = v[j] * scale[i] * rinv;
        const bf16 hh = __float2bfloat16(y);
        yh[rb + i] = hh;
        yl[rb + i] = __float2bfloat16(y - __bfloat162float(hh));
    }
}

// ---------------- fc1 reduce: +bias, gelu, pair split ----------------
__global__ void reduce_gelu_pair(const float* __restrict__ part, size_t ps, int S,
                                 const float* __restrict__ bias,
                                 bf16* __restrict__ oh, bf16* __restrict__ ol,
                                 int n4, int N) {
    int i = blockIdx.x * 256 + threadIdx.x;
    if (i >= n4) return;
    const size_t b = (size_t)i * 4;
    float4 a = *(const float4*)(part + b);
    for (int s = 1; s < S; s++) {
        const float4 p = *(const float4*)(part + (size_t)s * ps + b);
        a.x += p.x; a.y += p.y; a.z += p.z; a.w += p.w;
    }
    const float4 bb = *(const float4*)(bias + (int)(b % N));
    float v[4] = { a.x + bb.x, a.y + bb.y, a.z + bb.z, a.w + bb.w };
    bf16 hh[4], ll[4];
#pragma unroll
    for (int j = 0; j < 4; j++) {
        const float gv = 0.5f * v[j] * (1.f + erff(v[j] * 0.7071067811865475f));
        hh[j] = __float2bfloat16(gv);
        ll[j] = __float2bfloat16(gv - __bfloat162float(hh[j]));
    }
    *(__nv_bfloat162*)(oh + b)     = __nv_bfloat162(hh[0], hh[1]);
    *(__nv_bfloat162*)(oh + b + 2) = __nv_bfloat162(hh[2], hh[3]);
    *(__nv_bfloat162*)(ol + b)     = __nv_bfloat162(ll[0], ll[1]);
    *(__nv_bfloat162*)(ol + b + 2) = __nv_bfloat162(ll[2], ll[3]);
}

// ---------------- silu(gate)*up + bf16 hi/lo split ----------------
__global__ void silu_mul_quant(const float* __restrict__ GU,
                               bf16* __restrict__ Uh, bf16* __restrict__ Ul)
{
    const int row = blockIdx.x;
    const float* gr = GU + (size_t)row * FF2;
    bf16* uh = Uh + (size_t)row * FF_PAD;
    bf16* ul = Ul + (size_t)row * FF_PAD;
    for (int i = threadIdx.x; i < FF_PAD; i += 256) {
        float v = 0.f;
        if (i < FF_DIM) {
            const float gv = gr[i];
            v = (gv / (1.f + __expf(-gv))) * gr[FF_PAD + i];
        }
        const bf16 h = __float2bfloat16(v);
        uh[i] = h;
        ul[i] = __float2bfloat16(v - __bfloat162float(h));
    }
}

// ---------------- attention: fused qkv split-K(S=2) reduce + bias + RoPE ----------------
#define ATT_SMEM ((64 * 80 + 64 * 81 + 64 * 80 + 8 * 64) * 4)

__global__ void attn_kernel(const float* __restrict__ part, size_t ps,
                            const float* __restrict__ qkvb,
                            const float* __restrict__ rot,
                            bf16* __restrict__ oh, bf16* __restrict__ ol)
{
    extern __shared__ float sm[];
    float* qs = sm;
    float* ks = qs + 64 * 80;
    float* vs = ks + 64 * 81;
    float* pr = vs + 64 * 80;
    const int w = blockIdx.x, hh = blockIdx.y;
    const int tid = threadIdx.x, lane = tid & 31, warp = tid >> 5;
    const size_t base = (size_t)w * WIN * (3 * D_MODEL) + hh * HD;
    const int cb = hh * HD;

    for (int idx = tid; idx < WIN * HALF; idx += 256) {
        const int t = idx / HALF, d = idx % HALF;
        float s, c;
        sincosf(rot[(w * WIN + t) * HALF + d], &s, &c);
        const size_t g = base + (size_t)t * (3 * D_MODEL) + d;
        const float qre = part[g] + part[ps + g] + qkvb[cb + d];
        const float qim = part[g + HALF] + part[ps + g + HALF] + qkvb[cb + d + HALF];
        const float kre = part[g + D_MODEL] + part[ps + g + D_MODEL] + qkvb[cb + d + D_MODEL];
        const float kim = part[g + D_MODEL + HALF] + part[ps + g + D_MODEL + HALF]
                        + qkvb[cb + d + D_MODEL + HALF];
        qs[t * 80 + d]        = qre * c - qim * s;
        qs[t * 80 + d + HALF] = qre * s + qim * c;
        ks[t * 81 + d]        = kre * c - kim * s;
        ks[t * 81 + d + HALF] = kre * s + kim * c;
    }
    for (int idx = tid; idx < WIN * HD; idx += 256) {
        const int t = idx / HD, d = idx % HD;
        const size_t g = base + (size_t)t * (3 * D_MODEL) + 2 * D_MODEL + d;
        vs[t * 80 + d] = part[g] + part[ps + g] + qkvb[cb + d + 2 * D_MODEL];
    }
    __syncthreads();

    for (int row = warp; row < WIN; row += 8) {
        const float* qr = qs + row * 80;
        const float* k0 = ks + lane * 81;
        const float* k1 = ks + (lane + 32) * 81;
        float s0 = 0.f, s1 = 0.f;
#pragma unroll
        for (int d = 0; d < HD; d++) { const float q = qr[d]; s0 += q * k0[d]; s1 += q * k1[d]; }
        s0 *= ATT_SCALE; s1 *= ATT_SCALE;
        float mx = fmaxf(s0, s1);
#pragma unroll
        for (int o = 16; o; o >>= 1) mx = fmaxf(mx, __shfl_xor_sync(~0u, mx, o));
        const float e0 = __expf(s0 - mx), e1 = __expf(s1 - mx);
        float sum = e0 + e1;
#pragma unroll
        for (int o = 16; o; o >>= 1) sum += __shfl_xor_sync(~0u, sum, o);
        const float inv = 1.f / sum;
        pr[warp * 64 + lane] = e0 * inv;
        pr[warp * 64 + lane + 32] = e1 * inv;
        __syncwarp();
        float o0 = 0.f, o1 = 0.f, o2 = 0.f;
#pragma unroll 4
        for (int j = 0; j < WIN; j++) {
            const float p = pr[warp * 64 + j];
            const float* vr = vs + j * 80;
            o0 += p * vr[lane];
            o1 += p * vr[lane + 32];
            if (lane < 16) o2 += p * vr[lane + 64];
        }
        const size_t ob = (size_t)(w * WIN + row) * D_MODEL + hh * HD;
        bf16 h;
        h = __float2bfloat16(o0); oh[ob + lane] = h;
        ol[ob + lane] = __float2bfloat16(o0 - __bfloat162float(h));
        h = __float2bfloat16(o1); oh[ob + lane + 32] = h;
        ol[ob + lane + 32] = __float2bfloat16(o1 - __bfloat162float(h));
        if (lane < 16) {
            h = __float2bfloat16(o2); oh[ob + lane + 64] = h;
            ol[ob + lane + 64] = __float2bfloat16(o2 - __bfloat162float(h));
        }
        __syncwarp();
    }
}

// ---------------- host ----------------
extern "C" void kernel_launch(void* const* d_in, const int* in_sizes, int n_in,
                              void* d_out, int out_size)
{
    const float* x      = (const float*)d_in[0];
    const float* rot    = (const float*)d_in[1];
    const float* patchw = (const float*)d_in[3];
    const float* qkvw   = (const float*)d_in[4];
    const float* qkvb   = (const float*)d_in[5];
    const float* projw  = (const float*)d_in[6];
    const float* projb  = (const float*)d_in[7];
    const float* n1s    = (const float*)d_in[8];
    const float* n2s    = (const float*)d_in[9];
    const float* gw     = (const float*)d_in[10];
    const float* gb     = (const float*)d_in[11];
    const float* uw     = (const float*)d_in[12];
    const float* ub     = (const float*)d_in[13];
    const float* dw     = (const float*)d_in[14];
    const float* db     = (const float*)d_in[15];
    const float* lnq    = (const float*)d_in[16];
    const float* f1w    = (const float*)d_in[17];
    const float* f1b    = (const float*)d_in[18];
    const float* f2w    = (const float*)d_in[19];
    const float* f2b    = (const float*)d_in[20];
    float* out = (float*)d_out;

    float *h, *gu, *gub, *part;
    bf16 *xh, *xl, *nh, *nl, *ath, *atl, *uph, *upl, *f1h, *f1l;
    bf16 *patchTh, *patchTl, *qkvTh, *qkvTl, *projTh, *projTl;
    bf16 *guTh, *guTl, *downTh, *downTl, *fc1Th, *fc1Tl, *fc2Th, *fc2Tl;
#define GA(p, s) cudaGetSymbolAddress((void**)&p, s)
    GA(h, g_h); GA(gu, g_gu); GA(gub, g_gub); GA(part, g_part);
    GA(xh, g_xh); GA(xl, g_xl); GA(nh, g_nh); GA(nl, g_nl);
    GA(ath, g_ath); GA(atl, g_atl); GA(uph, g_uph); GA(upl, g_upl);
    GA(f1h, g_f1h); GA(f1l, g_f1l);
    GA(patchTh, g_patchTh); GA(patchTl, g_patchTl);
    GA(qkvTh, g_qkvTh); GA(qkvTl, g_qkvTl);
    GA(projTh, g_projTh); GA(projTl, g_projTl);
    GA(guTh, g_guTh); GA(guTl, g_guTl);
    GA(downTh, g_downTh); GA(downTl, g_downTl);
    GA(fc1Th, g_fc1Th); GA(fc1Tl, g_fc1Tl);
    GA(fc2Th, g_fc2Th); GA(fc2Tl, g_fc2Tl);
#undef GA

    cudaFuncSetAttribute(attn_kernel, cudaFuncAttributeMaxDynamicSharedMemorySize, ATT_SMEM);
    cudaFuncSetAttribute(gemm_bias, cudaFuncAttributeMaxDynamicSharedMemorySize, GEMM_SMEM);
    cudaFuncSetAttribute(gemm_part, cudaFuncAttributeMaxDynamicSharedMemorySize, GEMM_SMEM);

    // ---- setup: splits + weight conversion ----
    conv_act<<<(T_TOK * PATCH_KP + 255) / 256, 256>>>(x, xh, xl, T_TOK, PATCH_IN, PATCH_KP);
    build_gub<<<(DEPTH * FF2 + 255) / 256, 256>>>(gb, ub);
    {
        ConvTable tb;
        int tc = 0, si = 0;
        auto add = [&](const float* s, bf16* dh, bf16* dl, int K, int N, int Kp, int Np) {
            const int tx = (Kp + 31) / 32, ty = (Np + 31) / 32;
            tb.seg[si] = { s, dh, dl, K, N, Kp, tc, tx };
            tc += tx * ty; si++;
        };
        add(patchw, patchTh, patchTl, PATCH_IN, 1280, PATCH_KP, 1280);
        for (int l = 0; l < DEPTH; l++) {
            add(qkvw + (size_t)l * 1280 * 3840, qkvTh + (size_t)l * 3840 * 1280,
                qkvTl + (size_t)l * 3840 * 1280, 1280, 3840, 1280, 3840);
            add(projw + (size_t)l * 1280 * 1280, projTh + (size_t)l * 1280 * 1280,
                projTl + (size_t)l * 1280 * 1280, 1280, 1280, 1280, 1280);
            add(gw + (size_t)l * 1280 * FF_DIM, guTh + (size_t)l * FF2 * 1280,
                guTl + (size_t)l * FF2 * 1280, 1280, FF_DIM, 1280, FF_PAD);
            add(uw + (size_t)l * 1280 * FF_DIM,
                guTh + (size_t)l * FF2 * 1280 + (size_t)FF_PAD * 1280,
                guTl + (size_t)l * FF2 * 1280 + (size_t)FF_PAD * 1280,
                1280, FF_DIM, 1280, FF_PAD);
            add(dw + (size_t)l * FF_DIM * 1280, downTh + (size_t)l * 1280 * FF_PAD,
                downTl + (size_t)l * 1280 * FF_PAD, FF_DIM, 1280, FF_PAD, 1280);
        }
        add(f1w, fc1Th, fc1Tl, 5120, 5120, 5120, 5120);
        add(f2w, fc2Th, fc2Tl, 5120, 3584, 5120, 3584);
        conv_all<<<tc, dim3(32, 8)>>>(tb);
    }

    const size_t psD = (size_t)T_TOK * D_MODEL;
    const size_t psQ = (size_t)T_TOK * 3 * D_MODEL;
    const size_t psF = (size_t)512 * 5120;
    const int n4F = 512 * 5120 / 4;

    // ---- patch embed: split-K4 + fused reduce/rmsnorm(n1 layer0) ----
    gemm_part<<<dim3(16, 10, 4), 256, GEMM_SMEM>>>(
        xh, xl, patchTh, patchTl, part, psD, PATCH_KP, 1280);
    reduce_rms<false><<<T_TOK, 256>>>(part, psD, 4, nullptr, n1s, h, nh, nl);

    for (int l = 0; l < DEPTH; l++) {
        const size_t lD = (size_t)l * D_MODEL;
        // qkv: split-K2; reduction fused into attention
        gemm_part<<<dim3(16, 30, 2), 256, GEMM_SMEM>>>(
            nh, nl, qkvTh + (size_t)l * 3840 * 1280, qkvTl + (size_t)l * 3840 * 1280,
            part, psQ, 1280, 3840);
        attn_kernel<<<dim3(NWIN, H_HEADS), 256, ATT_SMEM>>>(
            part, psQ, qkvb + (size_t)l * 3840, rot, ath, atl);
        // proj: split-K4, then fused reduce+res+rmsnorm(n2)
        gemm_part<<<dim3(16, 10, 4), 256, GEMM_SMEM>>>(
            ath, atl, projTh + (size_t)l * 1280 * 1280, projTl + (size_t)l * 1280 * 1280,
            part, psD, 1280, 1280);
        reduce_rms<true><<<T_TOK, 256>>>(part, psD, 4, projb + lD, n2s + lD, h, nh, nl);
        // fused gate|up GEMM
        gemm_bias<<<dim3(16, FF2 / 128), 256, GEMM_SMEM>>>(
            nh, nl, guTh + (size_t)l * FF2 * 1280, guTl + (size_t)l * FF2 * 1280,
            gub + (size_t)l * FF2, gu, 1280, FF2);
        silu_mul_quant<<<T_TOK, 256>>>(gu, uph, upl);
        // down: split-K4, then fused reduce+res+rmsnorm(next n1 or lnq)
        gemm_part<<<dim3(16, 10, 4), 256, GEMM_SMEM>>>(
            uph, upl, downTh + (size_t)l * 1280 * FF_PAD, downTl + (size_t)l * 1280 * FF_PAD,
            part, psD, FF_PAD, 1280);
        const float* nexts = (l < DEPTH - 1) ? (n1s + (size_t)(l + 1) * D_MODEL) : lnq;
        reduce_rms<true><<<T_TOK, 256>>>(part, psD, 4, db + lD, nexts, h, nh, nl);
    }

    // ---- merger (nh/nl viewed as [512, 5120]) ----
    gemm_part<<<dim3(4, 40, 8), 256, GEMM_SMEM>>>(
        nh, nl, fc1Th, fc1Tl, part, psF, 5120, 5120);
    reduce_gelu_pair<<<(n4F + 255) / 256, 256>>>(part, psF, 8, f1b, f1h, f1l, n4F, 5120);
    gemm_bias<<<dim3(4, 28), 256, GEMM_SMEM>>>(
        f1h, f1l, fc2Th, fc2Tl, f2b, out, 5120, 3584);
}

// round 14
// speedup vs baseline: 1.4984x; 1.0022x over previous
#include <cuda_runtime.h>
#include <cuda_bf16.h>
#include <math.h>
#include <stdint.h>

// ---------------- problem constants ----------------
#define T_TOK   2048
#define D_MODEL 1280
#define H_HEADS 16
#define HD      80
#define HALF    40
#define FF_DIM  3420
#define FF_PAD  3456
#define FF2     (2 * FF_PAD)          // 6912 fused gate|up
#define DEPTH   4
#define OUT_DIM 3584
#define PATCH_IN 1176
#define PATCH_KP 1216
#define WIN     64
#define NWIN    (T_TOK / WIN)
#define EPS_RMS 1e-6f
#define ATT_SCALE 0.1118033988749895f

typedef __nv_bfloat16 bf16;

// ---------------- helpers ----------------
__device__ __forceinline__ uint32_t smem_u32(const void* p) {
    uint32_t a;
    asm("{ .reg .u64 t; cvta.to.shared.u64 t, %1; cvt.u32.u64 %0, t; }" : "=r"(a) : "l"(p));
    return a;
}
__device__ __forceinline__ void cp_async16(uint32_t s, const void* g) {
    asm volatile("cp.async.cg.shared.global [%0], [%1], 16;" :: "r"(s), "l"(g));
}
#define CP_COMMIT() asm volatile("cp.async.commit_group;" ::: "memory")
#define CP_WAIT(n)  asm volatile("cp.async.wait_group %0;" :: "n"(n) : "memory")

__device__ __forceinline__ void ldm_x4(uint32_t& r0, uint32_t& r1, uint32_t& r2,
                                       uint32_t& r3, uint32_t addr) {
    asm volatile("ldmatrix.sync.aligned.m8n8.x4.shared.b16 {%0,%1,%2,%3}, [%4];"
                 : "=r"(r0), "=r"(r1), "=r"(r2), "=r"(r3) : "r"(addr));
}
__device__ __forceinline__ void mma16816(float* d, const uint32_t* a,
                                         uint32_t b0, uint32_t b1) {
    asm volatile("mma.sync.aligned.m16n8k16.row.col.f32.bf16.bf16.f32 "
                 "{%0,%1,%2,%3}, {%4,%5,%6,%7}, {%8,%9}, {%0,%1,%2,%3};"
                 : "+f"(d[0]), "+f"(d[1]), "+f"(d[2]), "+f"(d[3])
                 : "r"(a[0]), "r"(a[1]), "r"(a[2]), "r"(a[3]), "r"(b0), "r"(b1));
}
// swizzled smem byte offset for 32B rows (two 16B segs), conflict-free for ldmatrix
__device__ __forceinline__ uint32_t swz16(int row, int seg) {
    return (uint32_t)(row * 32 + ((seg ^ ((row >> 2) & 1)) << 4));
}

// ---------------- scratch ----------------
__device__ float g_h  [T_TOK * D_MODEL];
__device__ float g_gu [(size_t)T_TOK * FF2];
__device__ float g_gub[DEPTH * FF2];
__device__ float g_part[(size_t)8 * 512 * 5120];   // split-K partials
__device__ bf16  g_xh [T_TOK * PATCH_KP],       g_xl [T_TOK * PATCH_KP];
__device__ bf16  g_nh [T_TOK * D_MODEL],        g_nl [T_TOK * D_MODEL];
__device__ bf16  g_ath[T_TOK * D_MODEL],        g_atl[T_TOK * D_MODEL];
__device__ bf16  g_uph[(size_t)T_TOK * FF_PAD], g_upl[(size_t)T_TOK * FF_PAD];
__device__ bf16  g_f1h[512 * 4 * D_MODEL],      g_f1l[512 * 4 * D_MODEL];
// transposed/split weights [N, Kp]
__device__ bf16 g_patchTh[1280 * PATCH_KP],              g_patchTl[1280 * PATCH_KP];
__device__ bf16 g_qkvTh [DEPTH * 3840 * 1280],           g_qkvTl [DEPTH * 3840 * 1280];
__device__ bf16 g_projTh[DEPTH * 1280 * 1280],           g_projTl[DEPTH * 1280 * 1280];
__device__ bf16 g_guTh  [(size_t)DEPTH * FF2 * 1280],    g_guTl  [(size_t)DEPTH * FF2 * 1280];
__device__ bf16 g_downTh[(size_t)DEPTH * 1280 * FF_PAD], g_downTl[(size_t)DEPTH * 1280 * FF_PAD];
__device__ bf16 g_fc1Th [5120 * 5120],                   g_fc1Tl [5120 * 5120];
__device__ bf16 g_fc2Th [3584 * 5120],                   g_fc2Tl [3584 * 5120];

// ---------------- activation split ----------------
__global__ void conv_act(const float* __restrict__ X, bf16* __restrict__ Xh,
                         bf16* __restrict__ Xl, int M, int K, int Kp) {
    int idx = blockIdx.x * 256 + threadIdx.x;
    if (idx >= M * Kp) return;
    int m = idx / Kp, k = idx - m * Kp;
    float v = (k < K) ? X[(size_t)m * K + k] : 0.f;
    bf16 h = __float2bfloat16(v);
    Xh[idx] = h;
    Xl[idx] = __float2bfloat16(v - __bfloat162float(h));
}

// ---------------- concat bias builder ----------------
__global__ void build_gub(const float* __restrict__ gb, const float* __restrict__ ub) {
    int idx = blockIdx.x * 256 + threadIdx.x;
    if (idx >= DEPTH * FF2) return;
    const int l = idx / FF2, c = idx - l * FF2;
    float v = 0.f;
    if (c < FF_DIM)                              v = gb[l * FF_DIM + c];
    else if (c >= FF_PAD && c < FF_PAD + FF_DIM) v = ub[l * FF_DIM + (c - FF_PAD)];
    g_gub[idx] = v;
}

// ---------------- batched weight transpose+split ----------------
#define NSEG 23
struct Seg { const float* s; bf16* dh; bf16* dl; int K, N, Kp, tile0, tilesX; };
struct ConvTable { Seg seg[NSEG]; };

__global__ void conv_all(ConvTable tb) {
    __shared__ float t[32][33];
    const int tile = blockIdx.x;
    int si = 0;
#pragma unroll
    for (int i = 1; i < NSEG; i++) si += (tb.seg[i].tile0 <= tile);
    const Seg sg = tb.seg[si];
    const int lt = tile - sg.tile0;
    const int kb = (lt % sg.tilesX) * 32;
    const int nb = (lt / sg.tilesX) * 32;
#pragma unroll
    for (int j = 0; j < 32; j += 8) {
        int k = kb + threadIdx.y + j, n = nb + threadIdx.x;
        t[threadIdx.y + j][threadIdx.x] =
            (k < sg.K && n < sg.N) ? sg.s[(size_t)k * sg.N + n] : 0.f;
    }
    __syncthreads();
#pragma unroll
    for (int j = 0; j < 32; j += 8) {
        int n = nb + threadIdx.y + j, k = kb + threadIdx.x;
        if (k < sg.Kp) {
            float v = t[threadIdx.x][threadIdx.y + j];
            bf16 h = __float2bfloat16(v);
            sg.dh[(size_t)n * sg.Kp + k] = h;
            sg.dl[(size_t)n * sg.Kp + k] = __float2bfloat16(v - __bfloat162float(h));
        }
    }
}

// ---------------- GEMM: fused-pass mainloop, k16 chunks, occ 2 ----------------
// Stage = Ah|Al|Bh|Bl, each 128 rows x 32B = 4 KB -> 16 KB/stage, 6 stages = 96 KB.
#define NSTAGE 6
#define STAGE_BYTES (4 * 128 * 32)            // 16384
#define GEMM_SMEM (NSTAGE * STAGE_BYTES)      // 98304 -> 2 CTAs/SM

#define GEMM_MAINLOOP(C0, C1)                                                      \
    loadChunk(C0 + 0, 0); loadChunk(C0 + 1, 1);                                    \
    loadChunk(C0 + 2, 2); loadChunk(C0 + 3, 3);                                    \
    for (int c = C0; c < C1; c += 2) {                                             \
        if (c + 2 < C1) { CP_WAIT(2); } else { CP_WAIT(0); }                       \
        __syncthreads();                                                           \
        if (c + 4 < C1) loadChunk(c + 4, (c + 4 - C0) % NSTAGE);                   \
        if (c + 5 < C1) loadChunk(c + 5, (c + 5 - C0) % NSTAGE);                   \
        computeChunk((c - C0) % NSTAGE);                                           \
        computeChunk((c + 1 - C0) % NSTAGE);                                       \
    }

#define GEMM_BODY_COMMON                                                           \
    const int kc = Kp >> 4;            /* k16 chunks */                            \
    const size_t rowB = (size_t)Kp * 2;                                            \
    const int ld_r = tid >> 1;         /* 0..127 */                                \
    const int ld_s = tid & 1;          /* 16B seg */                               \
    auto loadChunk = [&](int c, int buf) {                                         \
        const size_t kk = (size_t)c * 32;                                          \
        const size_t go = (size_t)ld_r * rowB + kk + ld_s * 16;                    \
        const uint32_t so = swz16(ld_r, ld_s);                                     \
        const uint32_t sAh = sbase + buf * STAGE_BYTES;                            \
        cp_async16(sAh + so,         (const char*)Ah + (size_t)row0 * rowB + go);  \
        cp_async16(sAh + 4096 + so,  (const char*)Al + (size_t)row0 * rowB + go);  \
        cp_async16(sAh + 8192 + so,  (const char*)Bh + (size_t)col0 * rowB + go);  \
        cp_async16(sAh + 12288 + so, (const char*)Bl + (size_t)col0 * rowB + go);  \
        CP_COMMIT();                                                               \
    };                                                                             \
    float acc[4][4][4];                                                            \
    _Pragma("unroll")                                                              \
    for (int i = 0; i < 4; i++)                                                    \
        _Pragma("unroll")                                                          \
        for (int j = 0; j < 4; j++)                                                \
            _Pragma("unroll")                                                      \
            for (int q = 0; q < 4; q++) acc[i][j][q] = 0.f;                        \
    const int a_row = warp_m * 64 + (lane & 15);                                   \
    const int a_seg = (lane >> 4);                                                 \
    const int b_row = warp_n * 32 + (lane & 7) + ((lane >> 4) << 3);               \
    const int b_seg = (lane >> 3) & 1;                                             \
    auto computeChunk = [&](int buf) {                                             \
        const uint32_t sAh = sbase + buf * STAGE_BYTES;                            \
        const uint32_t sAl = sAh + 4096;                                           \
        const uint32_t sBh = sAh + 8192;                                           \
        const uint32_t sBl = sAh + 12288;                                          \
        uint32_t ah[4][4], al[4][4], bh[2][4], bl[2][4];                           \
        /* all fragment loads issued up-front: LDSM latency hidden behind issues */\
        _Pragma("unroll")                                                          \
        for (int mi = 0; mi < 4; mi++)                                             \
            ldm_x4(ah[mi][0], ah[mi][1], ah[mi][2], ah[mi][3],                     \
                   sAh + swz16(a_row + mi * 16, a_seg));                           \
        _Pragma("unroll")                                                          \
        for (int j = 0; j < 2; j++)                                                \
            ldm_x4(bh[j][0], bh[j][1], bh[j][2], bh[j][3],                         \
                   sBh + swz16(b_row + j * 16, b_seg));                            \
        _Pragma("unroll")                                                          \
        for (int j = 0; j < 2; j++)                                                \
            ldm_x4(bl[j][0], bl[j][1], bl[j][2], bl[j][3],                         \
                   sBl + swz16(b_row + j * 16, b_seg));                            \
        _Pragma("unroll")                                                          \
        for (int mi = 0; mi < 4; mi++)                                             \
            ldm_x4(al[mi][0], al[mi][1], al[mi][2], al[mi][3],                     \
                   sAl + swz16(a_row + mi * 16, a_seg));                           \
        _Pragma("unroll")                                                          \
        for (int mi = 0; mi < 4; mi++)                                             \
            _Pragma("unroll")                                                      \
            for (int ni = 0; ni < 4; ni++)                                         \
                mma16816(acc[mi][ni], ah[mi],                                      \
                         bh[ni >> 1][(ni & 1) * 2], bh[ni >> 1][(ni & 1) * 2 + 1]);\
        _Pragma("unroll")                                                          \
        for (int mi = 0; mi < 4; mi++)                                             \
            _Pragma("unroll")                                                      \
            for (int ni = 0; ni < 4; ni++)                                         \
                mma16816(acc[mi][ni], ah[mi],                                      \
                         bl[ni >> 1][(ni & 1) * 2], bl[ni >> 1][(ni & 1) * 2 + 1]);\
        _Pragma("unroll")                                                          \
        for (int mi = 0; mi < 4; mi++)                                             \
            _Pragma("unroll")                                                      \
            for (int ni = 0; ni < 4; ni++)                                         \
                mma16816(acc[mi][ni], al[mi],                                      \
                         bh[ni >> 1][(ni & 1) * 2], bh[ni >> 1][(ni & 1) * 2 + 1]);\
    };

// ---- full GEMM with fused bias (gu, fc2; N multiple of 128) ----
__global__ __launch_bounds__(256, 2)
void gemm_bias(const bf16* __restrict__ Ah, const bf16* __restrict__ Al,
               const bf16* __restrict__ Bh, const bf16* __restrict__ Bl,
               const float* __restrict__ bias, float* __restrict__ C,
               int Kp, int N)
{
    extern __shared__ __align__(128) char smem[];
    const uint32_t sbase = smem_u32(smem);
    const int tid = threadIdx.x, lane = tid & 31, wid = tid >> 5;
    const int warp_m = wid >> 2, warp_n = wid & 3;
    const int row0 = blockIdx.x * 128, col0 = blockIdx.y * 128;

    GEMM_BODY_COMMON

    GEMM_MAINLOOP(0, kc)

    const int g = lane >> 2, tig = lane & 3;
#pragma unroll
    for (int mi = 0; mi < 4; mi++)
#pragma unroll
        for (int half = 0; half < 2; half++) {
            const int r = row0 + warp_m * 64 + mi * 16 + g + half * 8;
#pragma unroll
            for (int ni = 0; ni < 4; ni++) {
                const int col = col0 + warp_n * 32 + ni * 8 + tig * 2;
                const float2 bb = *(const float2*)(bias + col);
                *(float2*)(C + (size_t)r * N + col) =
                    make_float2(acc[mi][ni][half * 2 + 0] + bb.x,
                                acc[mi][ni][half * 2 + 1] + bb.y);
            }
        }
}

// ---- split-K GEMM: writes raw partials (grid.z = split index) ----
__global__ __launch_bounds__(256, 2)
void gemm_part(const bf16* __restrict__ Ah, const bf16* __restrict__ Al,
               const bf16* __restrict__ Bh, const bf16* __restrict__ Bl,
               float* __restrict__ part, size_t pstride,
               int Kp, int N)
{
    extern __shared__ __align__(128) char smem[];
    const uint32_t sbase = smem_u32(smem);
    const int tid = threadIdx.x, lane = tid & 31, wid = tid >> 5;
    const int warp_m = wid >> 2, warp_n = wid & 3;
    const int row0 = blockIdx.x * 128, col0 = blockIdx.y * 128;
    const int S = gridDim.z, sidx = blockIdx.z;

    GEMM_BODY_COMMON

    const int npair = kc >> 1;
    const int c0 = 2 * ((sidx * npair) / S);
    const int c1 = 2 * (((sidx + 1) * npair) / S);

    GEMM_MAINLOOP(c0, c1)

    float* P = part + (size_t)sidx * pstride;
    const int g = lane >> 2, tig = lane & 3;
#pragma unroll
    for (int mi = 0; mi < 4; mi++)
#pragma unroll
        for (int half = 0; half < 2; half++) {
            const int r = row0 + warp_m * 64 + mi * 16 + g + half * 8;
#pragma unroll
            for (int ni = 0; ni < 4; ni++) {
                const int col = col0 + warp_n * 32 + ni * 8 + tig * 2;
                *(float2*)(P + (size_t)r * N + col) =
                    make_float2(acc[mi][ni][half * 2 + 0], acc[mi][ni][half * 2 + 1]);
            }
        }
}

// ---------------- fused split-K reduce (+bias,+residual) + rmsnorm -> bf16 hi/lo ----------------
template <bool RES>
__global__ void reduce_rms(const float* __restrict__ part, size_t ps, int S,
                           const float* __restrict__ bias, const float* __restrict__ scale,
                           float* __restrict__ h, bf16* __restrict__ yh, bf16* __restrict__ yl)
{
    const int row = blockIdx.x;
    const size_t rb = (size_t)row * D_MODEL;
    float v[5];
    float sumsq = 0.f;
#pragma unroll
    for (int j = 0; j < 5; j++) {
        const int i = threadIdx.x + j * 256;
        float val = part[rb + i];
        for (int s = 1; s < S; s++) val += part[(size_t)s * ps + rb + i];
        if (RES) val += bias[i] + h[rb + i];
        h[rb + i] = val;
        v[j] = val;
        sumsq += val * val;
    }
#pragma unroll
    for (int o = 16; o; o >>= 1) sumsq += __shfl_xor_sync(~0u, sumsq, o);
    __shared__ float red[8];
    const int warp = threadIdx.x >> 5, lane = threadIdx.x & 31;
    if (lane == 0) red[warp] = sumsq;
    __syncthreads();
    if (warp == 0) {
        float t = (lane < 8) ? red[lane] : 0.f;
#pragma unroll
        for (int o = 4; o; o >>= 1) t += __shfl_xor_sync(~0u, t, o);
        if (lane == 0) red[0] = t;
    }
    __syncthreads();
    const float rinv = rsqrtf(red[0] * (1.f / D_MODEL) + EPS_RMS);
#pragma unroll
    for (int j = 0; j < 5; j++) {
        const int i = threadIdx.x + j * 256;
        const float y = v[j] * scale[i] * rinv;
        const bf16 hh = __float2bfloat16(y);
        yh[rb + i] = hh;
        yl[rb + i] = __float2bfloat16(y - __bfloat162float(hh));
    }
}

// ---------------- fc1 reduce: +bias, gelu, pair split ----------------
__global__ void reduce_gelu_pair(const float* __restrict__ part, size_t ps, int S,
                                 const float* __restrict__ bias,
                                 bf16* __restrict__ oh, bf16* __restrict__ ol,
                                 int n4, int N) {
    int i = blockIdx.x * 256 + threadIdx.x;
    if (i >= n4) return;
    const size_t b = (size_t)i * 4;
    float4 a = *(const float4*)(part + b);
    for (int s = 1; s < S; s++) {
        const float4 p = *(const float4*)(part + (size_t)s * ps + b);
        a.x += p.x; a.y += p.y; a.z += p.z; a.w += p.w;
    }
    const float4 bb = *(const float4*)(bias + (int)(b % N));
    float v[4] = { a.x + bb.x, a.y + bb.y, a.z + bb.z, a.w + bb.w };
    bf16 hh[4], ll[4];
#pragma unroll
    for (int j = 0; j < 4; j++) {
        const float gv = 0.5f * v[j] * (1.f + erff(v[j] * 0.7071067811865475f));
        hh[j] = __float2bfloat16(gv);
        ll[j] = __float2bfloat16(gv - __bfloat162float(hh[j]));
    }
    *(__nv_bfloat162*)(oh + b)     = __nv_bfloat162(hh[0], hh[1]);
    *(__nv_bfloat162*)(oh + b + 2) = __nv_bfloat162(hh[2], hh[3]);
    *(__nv_bfloat162*)(ol + b)     = __nv_bfloat162(ll[0], ll[1]);
    *(__nv_bfloat162*)(ol + b + 2) = __nv_bfloat162(ll[2], ll[3]);
}

// ---------------- silu(gate)*up + bf16 hi/lo split ----------------
__global__ void silu_mul_quant(const float* __restrict__ GU,
                               bf16* __restrict__ Uh, bf16* __restrict__ Ul)
{
    const int row = blockIdx.x;
    const float* gr = GU + (size_t)row * FF2;
    bf16* uh = Uh + (size_t)row * FF_PAD;
    bf16* ul = Ul + (size_t)row * FF_PAD;
    for (int i = threadIdx.x; i < FF_PAD; i += 256) {
        float v = 0.f;
        if (i < FF_DIM) {
            const float gv = gr[i];
            v = (gv / (1.f + __expf(-gv))) * gr[FF_PAD + i];
        }
        const bf16 h = __float2bfloat16(v);
        uh[i] = h;
        ul[i] = __float2bfloat16(v - __bfloat162float(h));
    }
}

// ---------------- attention: fused qkv split-K(S=2) reduce + bias + RoPE ----------------
#define ATT_SMEM ((64 * 80 + 64 * 81 + 64 * 80 + 8 * 64) * 4)

__global__ void attn_kernel(const float* __restrict__ part, size_t ps,
                            const float* __restrict__ qkvb,
                            const float* __restrict__ rot,
                            bf16* __restrict__ oh, bf16* __restrict__ ol)
{
    extern __shared__ float sm[];
    float* qs = sm;
    float* ks = qs + 64 * 80;
    float* vs = ks + 64 * 81;
    float* pr = vs + 64 * 80;
    const int w = blockIdx.x, hh = blockIdx.y;
    const int tid = threadIdx.x, lane = tid & 31, warp = tid >> 5;
    const size_t base = (size_t)w * WIN * (3 * D_MODEL) + hh * HD;
    const int cb = hh * HD;

    for (int idx = tid; idx < WIN * HALF; idx += 256) {
        const int t = idx / HALF, d = idx % HALF;
        float s, c;
        sincosf(rot[(w * WIN + t) * HALF + d], &s, &c);
        const size_t g = base + (size_t)t * (3 * D_MODEL) + d;
        const float qre = part[g] + part[ps + g] + qkvb[cb + d];
        const float qim = part[g + HALF] + part[ps + g + HALF] + qkvb[cb + d + HALF];
        const float kre = part[g + D_MODEL] + part[ps + g + D_MODEL] + qkvb[cb + d + D_MODEL];
        const float kim = part[g + D_MODEL + HALF] + part[ps + g + D_MODEL + HALF]
                        + qkvb[cb + d + D_MODEL + HALF];
        qs[t * 80 + d]        = qre * c - qim * s;
        qs[t * 80 + d + HALF] = qre * s + qim * c;
        ks[t * 81 + d]        = kre * c - kim * s;
        ks[t * 81 + d + HALF] = kre * s + kim * c;
    }
    for (int idx = tid; idx < WIN * HD; idx += 256) {
        const int t = idx / HD, d = idx % HD;
        const size_t g = base + (size_t)t * (3 * D_MODEL) + 2 * D_MODEL + d;
        vs[t * 80 + d] = part[g] + part[ps + g] + qkvb[cb + d + 2 * D_MODEL];
    }
    __syncthreads();

    for (int row = warp; row < WIN; row += 8) {
        const float* qr = qs + row * 80;
        const float* k0 = ks + lane * 81;
        const float* k1 = ks + (lane + 32) * 81;
        float s0 = 0.f, s1 = 0.f;
#pragma unroll
        for (int d = 0; d < HD; d++) { const float q = qr[d]; s0 += q * k0[d]; s1 += q * k1[d]; }
        s0 *= ATT_SCALE; s1 *= ATT_SCALE;
        float mx = fmaxf(s0, s1);
#pragma unroll
        for (int o = 16; o; o >>= 1) mx = fmaxf(mx, __shfl_xor_sync(~0u, mx, o));
        const float e0 = __expf(s0 - mx), e1 = __expf(s1 - mx);
        float sum = e0 + e1;
#pragma unroll
        for (int o = 16; o; o >>= 1) sum += __shfl_xor_sync(~0u, sum, o);
        const float inv = 1.f / sum;
        pr[warp * 64 + lane] = e0 * inv;
        pr[warp * 64 + lane + 32] = e1 * inv;
        __syncwarp();
        float o0 = 0.f, o1 = 0.f, o2 = 0.f;
#pragma unroll 4
        for (int j = 0; j < WIN; j++) {
            const float p = pr[warp * 64 + j];
            const float* vr = vs + j * 80;
            o0 += p * vr[lane];
            o1 += p * vr[lane + 32];
            if (lane < 16) o2 += p * vr[lane + 64];
        }
        const size_t ob = (size_t)(w * WIN + row) * D_MODEL + hh * HD;
        bf16 h;
        h = __float2bfloat16(o0); oh[ob + lane] = h;
        ol[ob + lane] = __float2bfloat16(o0 - __bfloat162float(h));
        h = __float2bfloat16(o1); oh[ob + lane + 32] = h;
        ol[ob + lane + 32] = __float2bfloat16(o1 - __bfloat162float(h));
        if (lane < 16) {
            h = __float2bfloat16(o2); oh[ob + lane + 64] = h;
            ol[ob + lane + 64] = __float2bfloat16(o2 - __bfloat162float(h));
        }
        __syncwarp();
    }
}

// ---------------- host ----------------
extern "C" void kernel_launch(void* const* d_in, const int* in_sizes, int n_in,
                              void* d_out, int out_size)
{
    const float* x      = (const float*)d_in[0];
    const float* rot    = (const float*)d_in[1];
    const float* patchw = (const float*)d_in[3];
    const float* qkvw   = (const float*)d_in[4];
    const float* qkvb   = (const float*)d_in[5];
    const float* projw  = (const float*)d_in[6];
    const float* projb  = (const float*)d_in[7];
    const float* n1s    = (const float*)d_in[8];
    const float* n2s    = (const float*)d_in[9];
    const float* gw     = (const float*)d_in[10];
    const float* gb     = (const float*)d_in[11];
    const float* uw     = (const float*)d_in[12];
    const float* ub     = (const float*)d_in[13];
    const float* dw     = (const float*)d_in[14];
    const float* db     = (const float*)d_in[15];
    const float* lnq    = (const float*)d_in[16];
    const float* f1w    = (const float*)d_in[17];
    const float* f1b    = (const float*)d_in[18];
    const float* f2w    = (const float*)d_in[19];
    const float* f2b    = (const float*)d_in[20];
    float* out = (float*)d_out;

    float *h, *gu, *gub, *part;
    bf16 *xh, *xl, *nh, *nl, *ath, *atl, *uph, *upl, *f1h, *f1l;
    bf16 *patchTh, *patchTl, *qkvTh, *qkvTl, *projTh, *projTl;
    bf16 *guTh, *guTl, *downTh, *downTl, *fc1Th, *fc1Tl, *fc2Th, *fc2Tl;
#define GA(p, s) cudaGetSymbolAddress((void**)&p, s)
    GA(h, g_h); GA(gu, g_gu); GA(gub, g_gub); GA(part, g_part);
    GA(xh, g_xh); GA(xl, g_xl); GA(nh, g_nh); GA(nl, g_nl);
    GA(ath, g_ath); GA(atl, g_atl); GA(uph, g_uph); GA(upl, g_upl);
    GA(f1h, g_f1h); GA(f1l, g_f1l);
    GA(patchTh, g_patchTh); GA(patchTl, g_patchTl);
    GA(qkvTh, g_qkvTh); GA(qkvTl, g_qkvTl);
    GA(projTh, g_projTh); GA(projTl, g_projTl);
    GA(guTh, g_guTh); GA(guTl, g_guTl);
    GA(downTh, g_downTh); GA(downTl, g_downTl);
    GA(fc1Th, g_fc1Th); GA(fc1Tl, g_fc1Tl);
    GA(fc2Th, g_fc2Th); GA(fc2Tl, g_fc2Tl);
#undef GA

    cudaFuncSetAttribute(attn_kernel, cudaFuncAttributeMaxDynamicSharedMemorySize, ATT_SMEM);
    cudaFuncSetAttribute(gemm_bias, cudaFuncAttributeMaxDynamicSharedMemorySize, GEMM_SMEM);
    cudaFuncSetAttribute(gemm_part, cudaFuncAttributeMaxDynamicSharedMemorySize, GEMM_SMEM);

    // ---- setup: splits + weight conversion ----
    conv_act<<<(T_TOK * PATCH_KP + 255) / 256, 256>>>(x, xh, xl, T_TOK, PATCH_IN, PATCH_KP);
    build_gub<<<(DEPTH * FF2 + 255) / 256, 256>>>(gb, ub);
    {
        ConvTable tb;
        int tc = 0, si = 0;
        auto add = [&](const float* s, bf16* dh, bf16* dl, int K, int N, int Kp, int Np) {
            const int tx = (Kp + 31) / 32, ty = (Np + 31) / 32;
            tb.seg[si] = { s, dh, dl, K, N, Kp, tc, tx };
            tc += tx * ty; si++;
        };
        add(patchw, patchTh, patchTl, PATCH_IN, 1280, PATCH_KP, 1280);
        for (int l = 0; l < DEPTH; l++) {
            add(qkvw + (size_t)l * 1280 * 3840, qkvTh + (size_t)l * 3840 * 1280,
                qkvTl + (size_t)l * 3840 * 1280, 1280, 3840, 1280, 3840);
            add(projw + (size_t)l * 1280 * 1280, projTh + (size_t)l * 1280 * 1280,
                projTl + (size_t)l * 1280 * 1280, 1280, 1280, 1280, 1280);
            add(gw + (size_t)l * 1280 * FF_DIM, guTh + (size_t)l * FF2 * 1280,
                guTl + (size_t)l * FF2 * 1280, 1280, FF_DIM, 1280, FF_PAD);
            add(uw + (size_t)l * 1280 * FF_DIM,
                guTh + (size_t)l * FF2 * 1280 + (size_t)FF_PAD * 1280,
                guTl + (size_t)l * FF2 * 1280 + (size_t)FF_PAD * 1280,
                1280, FF_DIM, 1280, FF_PAD);
            add(dw + (size_t)l * FF_DIM * 1280, downTh + (size_t)l * 1280 * FF_PAD,
                downTl + (size_t)l * 1280 * FF_PAD, FF_DIM, 1280, FF_PAD, 1280);
        }
        add(f1w, fc1Th, fc1Tl, 5120, 5120, 5120, 5120);
        add(f2w, fc2Th, fc2Tl, 5120, 3584, 5120, 3584);
        conv_all<<<tc, dim3(32, 8)>>>(tb);
    }

    const size_t psD = (size_t)T_TOK * D_MODEL;
    const size_t psQ = (size_t)T_TOK * 3 * D_MODEL;
    const size_t psF = (size_t)512 * 5120;
    const int n4F = 512 * 5120 / 4;

    // ---- patch embed: split-K4 + fused reduce/rmsnorm(n1 layer0) ----
    gemm_part<<<dim3(16, 10, 4), 256, GEMM_SMEM>>>(
        xh, xl, patchTh, patchTl, part, psD, PATCH_KP, 1280);
    reduce_rms<false><<<T_TOK, 256>>>(part, psD, 4, nullptr, n1s, h, nh, nl);

    for (int l = 0; l < DEPTH; l++) {
        const size_t lD = (size_t)l * D_MODEL;
        // qkv: split-K2; reduction fused into attention
        gemm_part<<<dim3(16, 30, 2), 256, GEMM_SMEM>>>(
            nh, nl, qkvTh + (size_t)l * 3840 * 1280, qkvTl + (size_t)l * 3840 * 1280,
            part, psQ, 1280, 3840);
        attn_kernel<<<dim3(NWIN, H_HEADS), 256, ATT_SMEM>>>(
            part, psQ, qkvb + (size_t)l * 3840, rot, ath, atl);
        // proj: split-K4, then fused reduce+res+rmsnorm(n2)
        gemm_part<<<dim3(16, 10, 4), 256, GEMM_SMEM>>>(
            ath, atl, projTh + (size_t)l * 1280 * 1280, projTl + (size_t)l * 1280 * 1280,
            part, psD, 1280, 1280);
        reduce_rms<true><<<T_TOK, 256>>>(part, psD, 4, projb + lD, n2s + lD, h, nh, nl);
        // fused gate|up GEMM
        gemm_bias<<<dim3(16, FF2 / 128), 256, GEMM_SMEM>>>(
            nh, nl, guTh + (size_t)l * FF2 * 1280, guTl + (size_t)l * FF2 * 1280,
            gub + (size_t)l * FF2, gu, 1280, FF2);
        silu_mul_quant<<<T_TOK, 256>>>(gu, uph, upl);
        // down: split-K4, then fused reduce+res+rmsnorm(next n1 or lnq)
        gemm_part<<<dim3(16, 10, 4), 256, GEMM_SMEM>>>(
            uph, upl, downTh + (size_t)l * 1280 * FF_PAD, downTl + (size_t)l * 1280 * FF_PAD,
            part, psD, FF_PAD, 1280);
        const float* nexts = (l < DEPTH - 1) ? (n1s + (size_t)(l + 1) * D_MODEL) : lnq;
        reduce_rms<true><<<T_TOK, 256>>>(part, psD, 4, db + lD, nexts, h, nh, nl);
    }

    // ---- merger (nh/nl viewed as [512, 5120]) ----
    gemm_part<<<dim3(4, 40, 8), 256, GEMM_SMEM>>>(
        nh, nl, fc1Th, fc1Tl, part, psF, 5120, 5120);
    reduce_gelu_pair<<<(n4F + 255) / 256, 256>>>(part, psF, 8, f1b, f1h, f1l, n4F, 5120);
    gemm_bias<<<dim3(4, 28), 256, GEMM_SMEM>>>(
        f1h, f1l, fc2Th, fc2Tl, f2b, out, 5120, 3584);
}

// round 15
// speedup vs baseline: 1.5094x; 1.0074x over previous
#include <cuda_runtime.h>
#include <cuda_bf16.h>
#include <math.h>
#include <stdint.h>

// ---------------- problem constants ----------------
#define T_TOK   2048
#define D_MODEL 1280
#define H_HEADS 16
#define HD      80
#define HALF    40
#define FF_DIM  3420
#define FF_PAD  3456
#define FF2     (2 * FF_PAD)          // 6912 interleaved gate|up
#define DEPTH   4
#define OUT_DIM 3584
#define PATCH_IN 1176
#define PATCH_KP 1216
#define WIN     64
#define NWIN    (T_TOK / WIN)
#define EPS_RMS 1e-6f
#define ATT_SCALE 0.1118033988749895f

typedef __nv_bfloat16 bf16;

// ---------------- helpers ----------------
__device__ __forceinline__ uint32_t smem_u32(const void* p) {
    uint32_t a;
    asm("{ .reg .u64 t; cvta.to.shared.u64 t, %1; cvt.u32.u64 %0, t; }" : "=r"(a) : "l"(p));
    return a;
}
__device__ __forceinline__ void cp_async16(uint32_t s, const void* g) {
    asm volatile("cp.async.cg.shared.global [%0], [%1], 16;" :: "r"(s), "l"(g));
}
#define CP_COMMIT() asm volatile("cp.async.commit_group;" ::: "memory")
#define CP_WAIT(n)  asm volatile("cp.async.wait_group %0;" :: "n"(n) : "memory")

__device__ __forceinline__ void ldm_x4(uint32_t& r0, uint32_t& r1, uint32_t& r2,
                                       uint32_t& r3, uint32_t addr) {
    asm volatile("ldmatrix.sync.aligned.m8n8.x4.shared.b16 {%0,%1,%2,%3}, [%4];"
                 : "=r"(r0), "=r"(r1), "=r"(r2), "=r"(r3) : "r"(addr));
}
__device__ __forceinline__ void mma16816(float* d, const uint32_t* a,
                                         uint32_t b0, uint32_t b1) {
    asm volatile("mma.sync.aligned.m16n8k16.row.col.f32.bf16.bf16.f32 "
                 "{%0,%1,%2,%3}, {%4,%5,%6,%7}, {%8,%9}, {%0,%1,%2,%3};"
                 : "+f"(d[0]), "+f"(d[1]), "+f"(d[2]), "+f"(d[3])
                 : "r"(a[0]), "r"(a[1]), "r"(a[2]), "r"(a[3]), "r"(b0), "r"(b1));
}
// swizzled smem byte offset for 32B rows (two 16B segs), conflict-free for ldmatrix
__device__ __forceinline__ uint32_t swz16(int row, int seg) {
    return (uint32_t)(row * 32 + ((seg ^ ((row >> 2) & 1)) << 4));
}

// ---------------- scratch ----------------
__device__ float g_h  [T_TOK * D_MODEL];
__device__ float g_gub[DEPTH * FF2];
__device__ float g_part[(size_t)3 * T_TOK * 3 * D_MODEL];   // 23.6M floats: covers qkv S=3, fc1 S=8, D S=5
__device__ bf16  g_xh [T_TOK * PATCH_KP],       g_xl [T_TOK * PATCH_KP];
__device__ bf16  g_nh [T_TOK * D_MODEL],        g_nl [T_TOK * D_MODEL];
__device__ bf16  g_ath[T_TOK * D_MODEL],        g_atl[T_TOK * D_MODEL];
__device__ bf16  g_uph[(size_t)T_TOK * FF_PAD], g_upl[(size_t)T_TOK * FF_PAD];
__device__ bf16  g_f1h[512 * 4 * D_MODEL],      g_f1l[512 * 4 * D_MODEL];
// transposed/split weights [N, Kp]
__device__ bf16 g_patchTh[1280 * PATCH_KP],              g_patchTl[1280 * PATCH_KP];
__device__ bf16 g_qkvTh [DEPTH * 3840 * 1280],           g_qkvTl [DEPTH * 3840 * 1280];
__device__ bf16 g_projTh[DEPTH * 1280 * 1280],           g_projTl[DEPTH * 1280 * 1280];
__device__ bf16 g_guTh  [(size_t)DEPTH * FF2 * 1280],    g_guTl  [(size_t)DEPTH * FF2 * 1280];
__device__ bf16 g_downTh[(size_t)DEPTH * 1280 * FF_PAD], g_downTl[(size_t)DEPTH * 1280 * FF_PAD];
__device__ bf16 g_fc1Th [5120 * 5120],                   g_fc1Tl [5120 * 5120];
__device__ bf16 g_fc2Th [3584 * 5120],                   g_fc2Tl [3584 * 5120];

// ---------------- activation split ----------------
__global__ void conv_act(const float* __restrict__ X, bf16* __restrict__ Xh,
                         bf16* __restrict__ Xl, int M, int K, int Kp) {
    int idx = blockIdx.x * 256 + threadIdx.x;
    if (idx >= M * Kp) return;
    int m = idx / Kp, k = idx - m * Kp;
    float v = (k < K) ? X[(size_t)m * K + k] : 0.f;
    bf16 h = __float2bfloat16(v);
    Xh[idx] = h;
    Xl[idx] = __float2bfloat16(v - __bfloat162float(h));
}

// ---------------- interleaved gate|up bias builder ----------------
__global__ void build_gub(const float* __restrict__ gb, const float* __restrict__ ub) {
    int idx = blockIdx.x * 256 + threadIdx.x;
    if (idx >= DEPTH * FF2) return;
    const int l = idx / FF2, c = idx - l * FF2;
    const int f = c >> 1;
    float v = 0.f;
    if (f < FF_DIM) v = (c & 1) ? ub[l * FF_DIM + f] : gb[l * FF_DIM + f];
    g_gub[idx] = v;
}

// ---------------- batched weight transpose+split (with row stride/offset) ----------------
#define NSEG 23
struct Seg { const float* s; bf16* dh; bf16* dl; int K, N, Kp, tile0, tilesX, rstride, roff; };
struct ConvTable { Seg seg[NSEG]; };

__global__ void conv_all(ConvTable tb) {
    __shared__ float t[32][33];
    const int tile = blockIdx.x;
    int si = 0;
#pragma unroll
    for (int i = 1; i < NSEG; i++) si += (tb.seg[i].tile0 <= tile);
    const Seg sg = tb.seg[si];
    const int lt = tile - sg.tile0;
    const int kb = (lt % sg.tilesX) * 32;
    const int nb = (lt / sg.tilesX) * 32;
#pragma unroll
    for (int j = 0; j < 32; j += 8) {
        int k = kb + threadIdx.y + j, n = nb + threadIdx.x;
        t[threadIdx.y + j][threadIdx.x] =
            (k < sg.K && n < sg.N) ? sg.s[(size_t)k * sg.N + n] : 0.f;
    }
    __syncthreads();
#pragma unroll
    for (int j = 0; j < 32; j += 8) {
        int n = nb + threadIdx.y + j, k = kb + threadIdx.x;
        if (k < sg.Kp) {
            float v = t[threadIdx.x][threadIdx.y + j];
            bf16 h = __float2bfloat16(v);
            const size_t dr = (size_t)n * sg.rstride + sg.roff;
            sg.dh[dr * sg.Kp + k] = h;
            sg.dl[dr * sg.Kp + k] = __float2bfloat16(v - __bfloat162float(h));
        }
    }
}

// ---------------- GEMM: fused-pass mainloop, k16 chunks, occ 2 ----------------
#define NSTAGE 6
#define STAGE_BYTES (4 * 128 * 32)            // 16384
#define GEMM_SMEM (NSTAGE * STAGE_BYTES)      // 98304 -> 2 CTAs/SM

#define GEMM_MAINLOOP(C0, C1)                                                      \
    loadChunk(C0 + 0, 0); loadChunk(C0 + 1, 1);                                    \
    loadChunk(C0 + 2, 2); loadChunk(C0 + 3, 3);                                    \
    for (int c = C0; c < C1; c += 2) {                                             \
        if (c + 2 < C1) { CP_WAIT(2); } else { CP_WAIT(0); }                       \
        __syncthreads();                                                           \
        if (c + 4 < C1) loadChunk(c + 4, (c + 4 - C0) % NSTAGE);                   \
        if (c + 5 < C1) loadChunk(c + 5, (c + 5 - C0) % NSTAGE);                   \
        computeChunk((c - C0) % NSTAGE);                                           \
        computeChunk((c + 1 - C0) % NSTAGE);                                       \
    }

#define GEMM_BODY_COMMON                                                           \
    const int kc = Kp >> 4;            /* k16 chunks */                            \
    const size_t rowB = (size_t)Kp * 2;                                            \
    const int ld_r = tid >> 1;                                                     \
    const int ld_s = tid & 1;                                                      \
    auto loadChunk = [&](int c, int buf) {                                         \
        const size_t kk = (size_t)c * 32;                                          \
        const size_t go = (size_t)ld_r * rowB + kk + ld_s * 16;                    \
        const uint32_t so = swz16(ld_r, ld_s);                                     \
        const uint32_t sAh = sbase + buf * STAGE_BYTES;                            \
        cp_async16(sAh + so,         (const char*)Ah + (size_t)row0 * rowB + go);  \
        cp_async16(sAh + 4096 + so,  (const char*)Al + (size_t)row0 * rowB + go);  \
        cp_async16(sAh + 8192 + so,  (const char*)Bh + (size_t)col0 * rowB + go);  \
        cp_async16(sAh + 12288 + so, (const char*)Bl + (size_t)col0 * rowB + go);  \
        CP_COMMIT();                                                               \
    };                                                                             \
    float acc[4][4][4];                                                            \
    _Pragma("unroll")                                                              \
    for (int i = 0; i < 4; i++)                                                    \
        _Pragma("unroll")                                                          \
        for (int j = 0; j < 4; j++)                                                \
            _Pragma("unroll")                                                      \
            for (int q = 0; q < 4; q++) acc[i][j][q] = 0.f;                        \
    const int a_row = warp_m * 64 + (lane & 15);                                   \
    const int a_seg = (lane >> 4);                                                 \
    const int b_row = warp_n * 32 + (lane & 7) + ((lane >> 4) << 3);               \
    const int b_seg = (lane >> 3) & 1;                                             \
    auto computeChunk = [&](int buf) {                                             \
        const uint32_t sAh = sbase + buf * STAGE_BYTES;                            \
        const uint32_t sAl = sAh + 4096;                                           \
        const uint32_t sBh = sAh + 8192;                                           \
        const uint32_t sBl = sAh + 12288;                                          \
        uint32_t ah[4][4], al[4][4], bh[2][4], bl[2][4];                           \
        _Pragma("unroll")                                                          \
        for (int mi = 0; mi < 4; mi++)                                             \
            ldm_x4(ah[mi][0], ah[mi][1], ah[mi][2], ah[mi][3],                     \
                   sAh + swz16(a_row + mi * 16, a_seg));                           \
        _Pragma("unroll")                                                          \
        for (int j = 0; j < 2; j++)                                                \
            ldm_x4(bh[j][0], bh[j][1], bh[j][2], bh[j][3],                         \
                   sBh + swz16(b_row + j * 16, b_seg));                            \
        _Pragma("unroll")                                                          \
        for (int j = 0; j < 2; j++)                                                \
            ldm_x4(bl[j][0], bl[j][1], bl[j][2], bl[j][3],                         \
                   sBl + swz16(b_row + j * 16, b_seg));                            \
        _Pragma("unroll")                                                          \
        for (int mi = 0; mi < 4; mi++)                                             \
            ldm_x4(al[mi][0], al[mi][1], al[mi][2], al[mi][3],                     \
                   sAl + swz16(a_row + mi * 16, a_seg));                           \
        _Pragma("unroll")                                                          \
        for (int mi = 0; mi < 4; mi++)                                             \
            _Pragma("unroll")                                                      \
            for (int ni = 0; ni < 4; ni++)                                         \
                mma16816(acc[mi][ni], ah[mi],                                      \
                         bh[ni >> 1][(ni & 1) * 2], bh[ni >> 1][(ni & 1) * 2 + 1]);\
        _Pragma("unroll")                                                          \
        for (int mi = 0; mi < 4; mi++)                                             \
            _Pragma("unroll")                                                      \
            for (int ni = 0; ni < 4; ni++)                                         \
                mma16816(acc[mi][ni], ah[mi],                                      \
                         bl[ni >> 1][(ni & 1) * 2], bl[ni >> 1][(ni & 1) * 2 + 1]);\
        _Pragma("unroll")                                                          \
        for (int mi = 0; mi < 4; mi++)                                             \
            _Pragma("unroll")                                                      \
            for (int ni = 0; ni < 4; ni++)                                         \
                mma16816(acc[mi][ni], al[mi],                                      \
                         bh[ni >> 1][(ni & 1) * 2], bh[ni >> 1][(ni & 1) * 2 + 1]);\
    };

// ---- full GEMM; SILU=false: fp32 C=AB+bias; SILU=true: interleaved silu(g)*u -> bf16 pair ----
template <bool SILU>
__global__ __launch_bounds__(256, 2)
void gemm_bias(const bf16* __restrict__ Ah, const bf16* __restrict__ Al,
               const bf16* __restrict__ Bh, const bf16* __restrict__ Bl,
               const float* __restrict__ bias, float* __restrict__ C,
               bf16* __restrict__ Uh, bf16* __restrict__ Ul,
               int Kp, int N)
{
    extern __shared__ __align__(128) char smem[];
    const uint32_t sbase = smem_u32(smem);
    const int tid = threadIdx.x, lane = tid & 31, wid = tid >> 5;
    const int warp_m = wid >> 2, warp_n = wid & 3;
    const int row0 = blockIdx.x * 128, col0 = blockIdx.y * 128;

    GEMM_BODY_COMMON

    GEMM_MAINLOOP(0, kc)

    const int g = lane >> 2, tig = lane & 3;
#pragma unroll
    for (int mi = 0; mi < 4; mi++)
#pragma unroll
        for (int half = 0; half < 2; half++) {
            const int r = row0 + warp_m * 64 + mi * 16 + g + half * 8;
#pragma unroll
            for (int ni = 0; ni < 4; ni++) {
                const int col = col0 + warp_n * 32 + ni * 8 + tig * 2;
                const float2 bb = *(const float2*)(bias + col);
                const float v0 = acc[mi][ni][half * 2 + 0] + bb.x;
                const float v1 = acc[mi][ni][half * 2 + 1] + bb.y;
                if (SILU) {
                    const float rr = (v0 / (1.f + __expf(-v0))) * v1;
                    const bf16 hh = __float2bfloat16(rr);
                    const int f = col >> 1;
                    Uh[(size_t)r * FF_PAD + f] = hh;
                    Ul[(size_t)r * FF_PAD + f] =
                        __float2bfloat16(rr - __bfloat162float(hh));
                } else {
                    *(float2*)(C + (size_t)r * N + col) = make_float2(v0, v1);
                }
            }
        }
}

// ---- split-K GEMM: writes raw partials (grid.z = split index) ----
__global__ __launch_bounds__(256, 2)
void gemm_part(const bf16* __restrict__ Ah, const bf16* __restrict__ Al,
               const bf16* __restrict__ Bh, const bf16* __restrict__ Bl,
               float* __restrict__ part, size_t pstride,
               int Kp, int N)
{
    extern __shared__ __align__(128) char smem[];
    const uint32_t sbase = smem_u32(smem);
    const int tid = threadIdx.x, lane = tid & 31, wid = tid >> 5;
    const int warp_m = wid >> 2, warp_n = wid & 3;
    const int row0 = blockIdx.x * 128, col0 = blockIdx.y * 128;
    const int S = gridDim.z, sidx = blockIdx.z;

    GEMM_BODY_COMMON

    const int npair = kc >> 1;
    const int c0 = 2 * ((sidx * npair) / S);
    const int c1 = 2 * (((sidx + 1) * npair) / S);

    GEMM_MAINLOOP(c0, c1)

    float* P = part + (size_t)sidx * pstride;
    const int g = lane >> 2, tig = lane & 3;
#pragma unroll
    for (int mi = 0; mi < 4; mi++)
#pragma unroll
        for (int half = 0; half < 2; half++) {
            const int r = row0 + warp_m * 64 + mi * 16 + g + half * 8;
#pragma unroll
            for (int ni = 0; ni < 4; ni++) {
                const int col = col0 + warp_n * 32 + ni * 8 + tig * 2;
                *(float2*)(P + (size_t)r * N + col) =
                    make_float2(acc[mi][ni][half * 2 + 0], acc[mi][ni][half * 2 + 1]);
            }
        }
}

// ---------------- fused split-K reduce (+bias,+residual) + rmsnorm -> bf16 hi/lo ----------------
template <bool RES>
__global__ void reduce_rms(const float* __restrict__ part, size_t ps, int S,
                           const float* __restrict__ bias, const float* __restrict__ scale,
                           float* __restrict__ h, bf16* __restrict__ yh, bf16* __restrict__ yl)
{
    const int row = blockIdx.x;
    const size_t rb = (size_t)row * D_MODEL;
    float v[5];
    float sumsq = 0.f;
#pragma unroll
    for (int j = 0; j < 5; j++) {
        const int i = threadIdx.x + j * 256;
        float val = part[rb + i];
        for (int s = 1; s < S; s++) val += part[(size_t)s * ps + rb + i];
        if (RES) val += bias[i] + h[rb + i];
        h[rb + i] = val;
        v[j] = val;
        sumsq += val * val;
    }
#pragma unroll
    for (int o = 16; o; o >>= 1) sumsq += __shfl_xor_sync(~0u, sumsq, o);
    __shared__ float red[8];
    const int warp = threadIdx.x >> 5, lane = threadIdx.x & 31;
    if (lane == 0) red[warp] = sumsq;
    __syncthreads();
    if (warp == 0) {
        float t = (lane < 8) ? red[lane] : 0.f;
#pragma unroll
        for (int o = 4; o; o >>= 1) t += __shfl_xor_sync(~0u, t, o);
        if (lane == 0) red[0] = t;
    }
    __syncthreads();
    const float rinv = rsqrtf(red[0] * (1.f / D_MODEL) + EPS_RMS);
#pragma unroll
    for (int j = 0; j < 5; j++) {
        const int i = threadIdx.x + j * 256;
        const float y = v[j] * scale[i] * rinv;
        const bf16 hh = __float2bfloat16(y);
        yh[rb + i] = hh;
        yl[rb + i] = __float2bfloat16(y - __bfloat162float(hh));
    }
}

// ---------------- fc1 reduce: +bias, gelu, pair split ----------------
__global__ void reduce_gelu_pair(const float* __restrict__ part, size_t ps, int S,
                                 const float* __restrict__ bias,
                                 bf16* __restrict__ oh, bf16* __restrict__ ol,
                                 int n4, int N) {
    int i = blockIdx.x * 256 + threadIdx.x;
    if (i >= n4) return;
    const size_t b = (size_t)i * 4;
    float4 a = *(const float4*)(part + b);
    for (int s = 1; s < S; s++) {
        const float4 p = *(const float4*)(part + (size_t)s * ps + b);
        a.x += p.x; a.y += p.y; a.z += p.z; a.w += p.w;
    }
    const float4 bb = *(const float4*)(bias + (int)(b % N));
    float v[4] = { a.x + bb.x, a.y + bb.y, a.z + bb.z, a.w + bb.w };
    bf16 hh[4], ll[4];
#pragma unroll
    for (int j = 0; j < 4; j++) {
        const float gv = 0.5f * v[j] * (1.f + erff(v[j] * 0.7071067811865475f));
        hh[j] = __float2bfloat16(gv);
        ll[j] = __float2bfloat16(gv - __bfloat162float(hh[j]));
    }
    *(__nv_bfloat162*)(oh + b)     = __nv_bfloat162(hh[0], hh[1]);
    *(__nv_bfloat162*)(oh + b + 2) = __nv_bfloat162(hh[2], hh[3]);
    *(__nv_bfloat162*)(ol + b)     = __nv_bfloat162(ll[0], ll[1]);
    *(__nv_bfloat162*)(ol + b + 2) = __nv_bfloat162(ll[2], ll[3]);
}

// ---------------- fc2 reduce: +bias, fp32 out ----------------
__global__ void reduce_bias_out(const float* __restrict__ part, size_t ps, int S,
                                const float* __restrict__ bias, float* __restrict__ out,
                                int n4, int N) {
    int i = blockIdx.x * 256 + threadIdx.x;
    if (i >= n4) return;
    const size_t b = (size_t)i * 4;
    float4 a = *(const float4*)(part + b);
    for (int s = 1; s < S; s++) {
        const float4 p = *(const float4*)(part + (size_t)s * ps + b);
        a.x += p.x; a.y += p.y; a.z += p.z; a.w += p.w;
    }
    const float4 bb = *(const float4*)(bias + (int)(b % N));
    a.x += bb.x; a.y += bb.y; a.z += bb.z; a.w += bb.w;
    *(float4*)(out + b) = a;
}

// ---------------- attention: fused qkv split-K reduce + bias + RoPE ----------------
#define ATT_SMEM ((64 * 80 + 64 * 81 + 64 * 80 + 8 * 64) * 4)

__global__ void attn_kernel(const float* __restrict__ part, size_t ps, int S,
                            const float* __restrict__ qkvb,
                            const float* __restrict__ rot,
                            bf16* __restrict__ oh, bf16* __restrict__ ol)
{
    extern __shared__ float sm[];
    float* qs = sm;
    float* ks = qs + 64 * 80;
    float* vs = ks + 64 * 81;
    float* pr = vs + 64 * 80;
    const int w = blockIdx.x, hh = blockIdx.y;
    const int tid = threadIdx.x, lane = tid & 31, warp = tid >> 5;
    const size_t base = (size_t)w * WIN * (3 * D_MODEL) + hh * HD;
    const int cb = hh * HD;

    for (int idx = tid; idx < WIN * HALF; idx += 256) {
        const int t = idx / HALF, d = idx % HALF;
        float s, c;
        sincosf(rot[(w * WIN + t) * HALF + d], &s, &c);
        const size_t g = base + (size_t)t * (3 * D_MODEL) + d;
        float qre = qkvb[cb + d],               qim = qkvb[cb + d + HALF];
        float kre = qkvb[cb + d + D_MODEL],     kim = qkvb[cb + d + D_MODEL + HALF];
        for (int sp = 0; sp < S; sp++) {
            const size_t o = (size_t)sp * ps + g;
            qre += part[o];            qim += part[o + HALF];
            kre += part[o + D_MODEL];  kim += part[o + D_MODEL + HALF];
        }
        qs[t * 80 + d]        = qre * c - qim * s;
        qs[t * 80 + d + HALF] = qre * s + qim * c;
        ks[t * 81 + d]        = kre * c - kim * s;
        ks[t * 81 + d + HALF] = kre * s + kim * c;
    }
    for (int idx = tid; idx < WIN * HD; idx += 256) {
        const int t = idx / HD, d = idx % HD;
        const size_t g = base + (size_t)t * (3 * D_MODEL) + 2 * D_MODEL + d;
        float v = qkvb[cb + d + 2 * D_MODEL];
        for (int sp = 0; sp < S; sp++) v += part[(size_t)sp * ps + g];
        vs[t * 80 + d] = v;
    }
    __syncthreads();

    for (int row = warp; row < WIN; row += 8) {
        const float* qr = qs + row * 80;
        const float* k0 = ks + lane * 81;
        const float* k1 = ks + (lane + 32) * 81;
        float s0 = 0.f, s1 = 0.f;
#pragma unroll
        for (int d = 0; d < HD; d++) { const float q = qr[d]; s0 += q * k0[d]; s1 += q * k1[d]; }
        s0 *= ATT_SCALE; s1 *= ATT_SCALE;
        float mx = fmaxf(s0, s1);
#pragma unroll
        for (int o = 16; o; o >>= 1) mx = fmaxf(mx, __shfl_xor_sync(~0u, mx, o));
        const float e0 = __expf(s0 - mx), e1 = __expf(s1 - mx);
        float sum = e0 + e1;
#pragma unroll
        for (int o = 16; o; o >>= 1) sum += __shfl_xor_sync(~0u, sum, o);
        const float inv = 1.f / sum;
        pr[warp * 64 + lane] = e0 * inv;
        pr[warp * 64 + lane + 32] = e1 * inv;
        __syncwarp();
        float o0 = 0.f, o1 = 0.f, o2 = 0.f;
#pragma unroll 4
        for (int j = 0; j < WIN; j++) {
            const float p = pr[warp * 64 + j];
            const float* vr = vs + j * 80;
            o0 += p * vr[lane];
            o1 += p * vr[lane + 32];
            if (lane < 16) o2 += p * vr[lane + 64];
        }
        const size_t ob = (size_t)(w * WIN + row) * D_MODEL + hh * HD;
        bf16 h;
        h = __float2bfloat16(o0); oh[ob + lane] = h;
        ol[ob + lane] = __float2bfloat16(o0 - __bfloat162float(h));
        h = __float2bfloat16(o1); oh[ob + lane + 32] = h;
        ol[ob + lane + 32] = __float2bfloat16(o1 - __bfloat162float(h));
        if (lane < 16) {
            h = __float2bfloat16(o2); oh[ob + lane + 64] = h;
            ol[ob + lane + 64] = __float2bfloat16(o2 - __bfloat162float(h));
        }
        __syncwarp();
    }
}

// ---------------- host ----------------
extern "C" void kernel_launch(void* const* d_in, const int* in_sizes, int n_in,
                              void* d_out, int out_size)
{
    const float* x      = (const float*)d_in[0];
    const float* rot    = (const float*)d_in[1];
    const float* patchw = (const float*)d_in[3];
    const float* qkvw   = (const float*)d_in[4];
    const float* qkvb   = (const float*)d_in[5];
    const float* projw  = (const float*)d_in[6];
    const float* projb  = (const float*)d_in[7];
    const float* n1s    = (const float*)d_in[8];
    const float* n2s    = (const float*)d_in[9];
    const float* gw     = (const float*)d_in[10];
    const float* gb     = (const float*)d_in[11];
    const float* uw     = (const float*)d_in[12];
    const float* ub     = (const float*)d_in[13];
    const float* dw     = (const float*)d_in[14];
    const float* db     = (const float*)d_in[15];
    const float* lnq    = (const float*)d_in[16];
    const float* f1w    = (const float*)d_in[17];
    const float* f1b    = (const float*)d_in[18];
    const float* f2w    = (const float*)d_in[19];
    const float* f2b    = (const float*)d_in[20];
    float* out = (float*)d_out;

    float *h, *gub, *part;
    bf16 *xh, *xl, *nh, *nl, *ath, *atl, *uph, *upl, *f1h, *f1l;
    bf16 *patchTh, *patchTl, *qkvTh, *qkvTl, *projTh, *projTl;
    bf16 *guTh, *guTl, *downTh, *downTl, *fc1Th, *fc1Tl, *fc2Th, *fc2Tl;
#define GA(p, s) cudaGetSymbolAddress((void**)&p, s)
    GA(h, g_h); GA(gub, g_gub); GA(part, g_part);
    GA(xh, g_xh); GA(xl, g_xl); GA(nh, g_nh); GA(nl, g_nl);
    GA(ath, g_ath); GA(atl, g_atl); GA(uph, g_uph); GA(upl, g_upl);
    GA(f1h, g_f1h); GA(f1l, g_f1l);
    GA(patchTh, g_patchTh); GA(patchTl, g_patchTl);
    GA(qkvTh, g_qkvTh); GA(qkvTl, g_qkvTl);
    GA(projTh, g_projTh); GA(projTl, g_projTl);
    GA(guTh, g_guTh); GA(guTl, g_guTl);
    GA(downTh, g_downTh); GA(downTl, g_downTl);
    GA(fc1Th, g_fc1Th); GA(fc1Tl, g_fc1Tl);
    GA(fc2Th, g_fc2Th); GA(fc2Tl, g_fc2Tl);
#undef GA

    cudaFuncSetAttribute(attn_kernel, cudaFuncAttributeMaxDynamicSharedMemorySize, ATT_SMEM);
    cudaFuncSetAttribute(gemm_bias<false>, cudaFuncAttributeMaxDynamicSharedMemorySize, GEMM_SMEM);
    cudaFuncSetAttribute(gemm_bias<true>,  cudaFuncAttributeMaxDynamicSharedMemorySize, GEMM_SMEM);
    cudaFuncSetAttribute(gemm_part, cudaFuncAttributeMaxDynamicSharedMemorySize, GEMM_SMEM);

    // ---- setup: splits + weight conversion ----
    conv_act<<<(T_TOK * PATCH_KP + 255) / 256, 256>>>(x, xh, xl, T_TOK, PATCH_IN, PATCH_KP);
    build_gub<<<(DEPTH * FF2 + 255) / 256, 256>>>(gb, ub);
    {
        ConvTable tb;
        int tc = 0, si = 0;
        auto add = [&](const float* s, bf16* dh, bf16* dl, int K, int N, int Kp, int Np,
                       int rstride, int roff) {
            const int tx = (Kp + 31) / 32, ty = (Np + 31) / 32;
            tb.seg[si] = { s, dh, dl, K, N, Kp, tc, tx, rstride, roff };
            tc += tx * ty; si++;
        };
        add(patchw, patchTh, patchTl, PATCH_IN, 1280, PATCH_KP, 1280, 1, 0);
        for (int l = 0; l < DEPTH; l++) {
            add(qkvw + (size_t)l * 1280 * 3840, qkvTh + (size_t)l * 3840 * 1280,
                qkvTl + (size_t)l * 3840 * 1280, 1280, 3840, 1280, 3840, 1, 0);
            add(projw + (size_t)l * 1280 * 1280, projTh + (size_t)l * 1280 * 1280,
                projTl + (size_t)l * 1280 * 1280, 1280, 1280, 1280, 1280, 1, 0);
            // gate -> even interleaved rows, up -> odd interleaved rows
            add(gw + (size_t)l * 1280 * FF_DIM, guTh + (size_t)l * FF2 * 1280,
                guTl + (size_t)l * FF2 * 1280, 1280, FF_DIM, 1280, FF_PAD, 2, 0);
            add(uw + (size_t)l * 1280 * FF_DIM, guTh + (size_t)l * FF2 * 1280,
                guTl + (size_t)l * FF2 * 1280, 1280, FF_DIM, 1280, FF_PAD, 2, 1);
            add(dw + (size_t)l * FF_DIM * 1280, downTh + (size_t)l * 1280 * FF_PAD,
                downTl + (size_t)l * 1280 * FF_PAD, FF_DIM, 1280, FF_PAD, 1280, 1, 0);
        }
        add(f1w, fc1Th, fc1Tl, 5120, 5120, 5120, 5120, 1, 0);
        add(f2w, fc2Th, fc2Tl, 5120, 3584, 5120, 3584, 1, 0);
        conv_all<<<tc, dim3(32, 8)>>>(tb);
    }

    const size_t psD  = (size_t)T_TOK * D_MODEL;
    const size_t psQ  = (size_t)T_TOK * 3 * D_MODEL;
    const size_t psF  = (size_t)512 * 5120;
    const size_t psF2 = (size_t)512 * OUT_DIM;
    const int n4F  = 512 * 5120 / 4;
    const int n4F2 = 512 * OUT_DIM / 4;

    // ---- patch embed: split-K5 + fused reduce/rmsnorm(n1 layer0) ----
    gemm_part<<<dim3(16, 10, 5), 256, GEMM_SMEM>>>(
        xh, xl, patchTh, patchTl, part, psD, PATCH_KP, 1280);
    reduce_rms<false><<<T_TOK, 256>>>(part, psD, 5, nullptr, n1s, h, nh, nl);

    for (int l = 0; l < DEPTH; l++) {
        const size_t lD = (size_t)l * D_MODEL;
        // qkv: split-K3; reduction fused into attention
        gemm_part<<<dim3(16, 30, 3), 256, GEMM_SMEM>>>(
            nh, nl, qkvTh + (size_t)l * 3840 * 1280, qkvTl + (size_t)l * 3840 * 1280,
            part, psQ, 1280, 3840);
        attn_kernel<<<dim3(NWIN, H_HEADS), 256, ATT_SMEM>>>(
            part, psQ, 3, qkvb + (size_t)l * 3840, rot, ath, atl);
        // proj: split-K5, then fused reduce+res+rmsnorm(n2)
        gemm_part<<<dim3(16, 10, 5), 256, GEMM_SMEM>>>(
            ath, atl, projTh + (size_t)l * 1280 * 1280, projTl + (size_t)l * 1280 * 1280,
            part, psD, 1280, 1280);
        reduce_rms<true><<<T_TOK, 256>>>(part, psD, 5, projb + lD, n2s + lD, h, nh, nl);
        // fused gate|up GEMM with silu epilogue (interleaved cols)
        gemm_bias<true><<<dim3(16, FF2 / 128), 256, GEMM_SMEM>>>(
            nh, nl, guTh + (size_t)l * FF2 * 1280, guTl + (size_t)l * FF2 * 1280,
            gub + (size_t)l * FF2, nullptr, uph, upl, 1280, FF2);
        // down: split-K5, then fused reduce+res+rmsnorm(next n1 or lnq)
        gemm_part<<<dim3(16, 10, 5), 256, GEMM_SMEM>>>(
            uph, upl, downTh + (size_t)l * 1280 * FF_PAD, downTl + (size_t)l * 1280 * FF_PAD,
            part, psD, FF_PAD, 1280);
        const float* nexts = (l < DEPTH - 1) ? (n1s + (size_t)(l + 1) * D_MODEL) : lnq;
        reduce_rms<true><<<T_TOK, 256>>>(part, psD, 5, db + lD, nexts, h, nh, nl);
    }

    // ---- merger (nh/nl viewed as [512, 5120]) ----
    gemm_part<<<dim3(4, 40, 8), 256, GEMM_SMEM>>>(
        nh, nl, fc1Th, fc1Tl, part, psF, 5120, 5120);
    reduce_gelu_pair<<<(n4F + 255) / 256, 256>>>(part, psF, 8, f1b, f1h, f1l, n4F, 5120);
    // fc2: split-K4 + bias reduce to output
    gemm_part<<<dim3(4, 28, 4), 256, GEMM_SMEM>>>(
        f1h, f1l, fc2Th, fc2Tl, part, psF2, 5120, OUT_DIM);
    reduce_bias_out<<<(n4F2 + 255) / 256, 256>>>(part, psF2, 4, f2b, out, n4F2, OUT_DIM);
}

// round 16
// speedup vs baseline: 2.0078x; 1.3302x over previous
#include <cuda_runtime.h>
#include <cuda_fp16.h>
#include <math.h>
#include <stdint.h>

// ---------------- problem constants ----------------
#define T_TOK   2048
#define D_MODEL 1280
#define H_HEADS 16
#define HD      80
#define HALF    40
#define FF_DIM  3420
#define FF_PAD  3456
#define FF2     (2 * FF_PAD)          // 6912 interleaved gate|up
#define DEPTH   4
#define OUT_DIM 3584
#define PATCH_IN 1176
#define PATCH_KP 1216
#define WIN     64
#define NWIN    (T_TOK / WIN)
#define EPS_RMS 1e-6f
#define ATT_SCALE 0.1118033988749895f

typedef __half f16;

// ---------------- helpers ----------------
__device__ __forceinline__ uint32_t smem_u32(const void* p) {
    uint32_t a;
    asm("{ .reg .u64 t; cvta.to.shared.u64 t, %1; cvt.u32.u64 %0, t; }" : "=r"(a) : "l"(p));
    return a;
}
__device__ __forceinline__ void cp_async16(uint32_t s, const void* g) {
    asm volatile("cp.async.cg.shared.global [%0], [%1], 16;" :: "r"(s), "l"(g));
}
#define CP_COMMIT() asm volatile("cp.async.commit_group;" ::: "memory")
#define CP_WAIT(n)  asm volatile("cp.async.wait_group %0;" :: "n"(n) : "memory")

__device__ __forceinline__ void ldm_x4(uint32_t& r0, uint32_t& r1, uint32_t& r2,
                                       uint32_t& r3, uint32_t addr) {
    asm volatile("ldmatrix.sync.aligned.m8n8.x4.shared.b16 {%0,%1,%2,%3}, [%4];"
                 : "=r"(r0), "=r"(r1), "=r"(r2), "=r"(r3) : "r"(addr));
}
__device__ __forceinline__ void mma16816(float* d, const uint32_t* a,
                                         uint32_t b0, uint32_t b1) {
    asm volatile("mma.sync.aligned.m16n8k16.row.col.f32.f16.f16.f32 "
                 "{%0,%1,%2,%3}, {%4,%5,%6,%7}, {%8,%9}, {%0,%1,%2,%3};"
                 : "+f"(d[0]), "+f"(d[1]), "+f"(d[2]), "+f"(d[3])
                 : "r"(a[0]), "r"(a[1]), "r"(a[2]), "r"(a[3]), "r"(b0), "r"(b1));
}
// swizzled smem byte offset for 32B rows (two 16B segs), conflict-free for ldmatrix
__device__ __forceinline__ uint32_t swz16(int row, int seg) {
    return (uint32_t)(row * 32 + ((seg ^ ((row >> 2) & 1)) << 4));
}

// ---------------- scratch ----------------
__device__ float g_h  [T_TOK * D_MODEL];
__device__ float g_gub[DEPTH * FF2];
__device__ float g_part[(size_t)3 * T_TOK * 3 * D_MODEL];
__device__ f16  g_xh [T_TOK * PATCH_KP];
__device__ f16  g_nh [T_TOK * D_MODEL];
__device__ f16  g_ath[T_TOK * D_MODEL];
__device__ f16  g_uph[(size_t)T_TOK * FF_PAD];
__device__ f16  g_f1h[512 * 4 * D_MODEL];
// transposed/split weights [N, Kp] (hi + lo fp16)
__device__ f16 g_patchTh[1280 * PATCH_KP],              g_patchTl[1280 * PATCH_KP];
__device__ f16 g_qkvTh [DEPTH * 3840 * 1280],           g_qkvTl [DEPTH * 3840 * 1280];
__device__ f16 g_projTh[DEPTH * 1280 * 1280],           g_projTl[DEPTH * 1280 * 1280];
__device__ f16 g_guTh  [(size_t)DEPTH * FF2 * 1280],    g_guTl  [(size_t)DEPTH * FF2 * 1280];
__device__ f16 g_downTh[(size_t)DEPTH * 1280 * FF_PAD], g_downTl[(size_t)DEPTH * 1280 * FF_PAD];
__device__ f16 g_fc1Th [5120 * 5120],                   g_fc1Tl [5120 * 5120];
__device__ f16 g_fc2Th [3584 * 5120],                   g_fc2Tl [3584 * 5120];

// ---------------- activation convert (single fp16 plane) ----------------
__global__ void conv_act(const float* __restrict__ X, f16* __restrict__ Xh,
                         int M, int K, int Kp) {
    int idx = blockIdx.x * 256 + threadIdx.x;
    if (idx >= M * Kp) return;
    int m = idx / Kp, k = idx - m * Kp;
    float v = (k < K) ? X[(size_t)m * K + k] : 0.f;
    Xh[idx] = __float2half(v);
}

// ---------------- interleaved gate|up bias builder ----------------
__global__ void build_gub(const float* __restrict__ gb, const float* __restrict__ ub) {
    int idx = blockIdx.x * 256 + threadIdx.x;
    if (idx >= DEPTH * FF2) return;
    const int l = idx / FF2, c = idx - l * FF2;
    const int f = c >> 1;
    float v = 0.f;
    if (f < FF_DIM) v = (c & 1) ? ub[l * FF_DIM + f] : gb[l * FF_DIM + f];
    g_gub[idx] = v;
}

// ---------------- batched weight transpose+split (hi/lo fp16) ----------------
#define NSEG 23
struct Seg { const float* s; f16* dh; f16* dl; int K, N, Kp, tile0, tilesX, rstride, roff; };
struct ConvTable { Seg seg[NSEG]; };

__global__ void conv_all(ConvTable tb) {
    __shared__ float t[32][33];
    const int tile = blockIdx.x;
    int si = 0;
#pragma unroll
    for (int i = 1; i < NSEG; i++) si += (tb.seg[i].tile0 <= tile);
    const Seg sg = tb.seg[si];
    const int lt = tile - sg.tile0;
    const int kb = (lt % sg.tilesX) * 32;
    const int nb = (lt / sg.tilesX) * 32;
#pragma unroll
    for (int j = 0; j < 32; j += 8) {
        int k = kb + threadIdx.y + j, n = nb + threadIdx.x;
        t[threadIdx.y + j][threadIdx.x] =
            (k < sg.K && n < sg.N) ? sg.s[(size_t)k * sg.N + n] : 0.f;
    }
    __syncthreads();
#pragma unroll
    for (int j = 0; j < 32; j += 8) {
        int n = nb + threadIdx.y + j, k = kb + threadIdx.x;
        if (k < sg.Kp) {
            float v = t[threadIdx.x][threadIdx.y + j];
            f16 h = __float2half(v);
            const size_t dr = (size_t)n * sg.rstride + sg.roff;
            sg.dh[dr * sg.Kp + k] = h;
            sg.dl[dr * sg.Kp + k] = __float2half(v - __half2float(h));
        }
    }
}

// ---------------- GEMM: fp16 2-pass (Ah·Bh + Ah·Bl), k16 chunks, occ 2 ----------------
#define NSTAGE 6
#define STAGE_BYTES (3 * 128 * 32)            // 12288: Ah | Bh | Bl
#define GEMM_SMEM (NSTAGE * STAGE_BYTES)      // 73728 -> 2 CTAs/SM

#define GEMM_MAINLOOP(C0, C1)                                                      \
    loadChunk(C0 + 0, 0); loadChunk(C0 + 1, 1);                                    \
    loadChunk(C0 + 2, 2); loadChunk(C0 + 3, 3);                                    \
    for (int c = C0; c < C1; c += 2) {                                             \
        if (c + 2 < C1) { CP_WAIT(2); } else { CP_WAIT(0); }                       \
        __syncthreads();                                                           \
        if (c + 4 < C1) loadChunk(c + 4, (c + 4 - C0) % NSTAGE);                   \
        if (c + 5 < C1) loadChunk(c + 5, (c + 5 - C0) % NSTAGE);                   \
        computeChunk((c - C0) % NSTAGE);                                           \
        computeChunk((c + 1 - C0) % NSTAGE);                                       \
    }

#define GEMM_BODY_COMMON                                                           \
    const int kc = Kp >> 4;            /* k16 chunks */                            \
    const size_t rowB = (size_t)Kp * 2;                                            \
    const int ld_r = tid >> 1;                                                     \
    const int ld_s = tid & 1;                                                      \
    auto loadChunk = [&](int c, int buf) {                                         \
        const size_t kk = (size_t)c * 32;                                          \
        const size_t go = (size_t)ld_r * rowB + kk + ld_s * 16;                    \
        const uint32_t so = swz16(ld_r, ld_s);                                     \
        const uint32_t sA = sbase + buf * STAGE_BYTES;                             \
        cp_async16(sA + so,        (const char*)Ah + (size_t)row0 * rowB + go);    \
        cp_async16(sA + 4096 + so, (const char*)Bh + (size_t)col0 * rowB + go);    \
        cp_async16(sA + 8192 + so, (const char*)Bl + (size_t)col0 * rowB + go);    \
        CP_COMMIT();                                                               \
    };                                                                             \
    float acc[4][4][4];                                                            \
    _Pragma("unroll")                                                              \
    for (int i = 0; i < 4; i++)                                                    \
        _Pragma("unroll")                                                          \
        for (int j = 0; j < 4; j++)                                                \
            _Pragma("unroll")                                                      \
            for (int q = 0; q < 4; q++) acc[i][j][q] = 0.f;                        \
    const int a_row = warp_m * 64 + (lane & 15);                                   \
    const int a_seg = (lane >> 4);                                                 \
    const int b_row = warp_n * 32 + (lane & 7) + ((lane >> 4) << 3);               \
    const int b_seg = (lane >> 3) & 1;                                             \
    auto computeChunk = [&](int buf) {                                             \
        const uint32_t sA  = sbase + buf * STAGE_BYTES;                            \
        const uint32_t sBh = sA + 4096;                                            \
        const uint32_t sBl = sA + 8192;                                            \
        uint32_t ah[4][4], bh[2][4], bl[2][4];                                     \
        _Pragma("unroll")                                                          \
        for (int mi = 0; mi < 4; mi++)                                             \
            ldm_x4(ah[mi][0], ah[mi][1], ah[mi][2], ah[mi][3],                     \
                   sA + swz16(a_row + mi * 16, a_seg));                            \
        _Pragma("unroll")                                                          \
        for (int j = 0; j < 2; j++)                                                \
            ldm_x4(bh[j][0], bh[j][1], bh[j][2], bh[j][3],                         \
                   sBh + swz16(b_row + j * 16, b_seg));                            \
        _Pragma("unroll")                                                          \
        for (int j = 0; j < 2; j++)                                                \
            ldm_x4(bl[j][0], bl[j][1], bl[j][2], bl[j][3],                         \
                   sBl + swz16(b_row + j * 16, b_seg));                            \
        _Pragma("unroll")                                                          \
        for (int mi = 0; mi < 4; mi++)                                             \
            _Pragma("unroll")                                                      \
            for (int ni = 0; ni < 4; ni++)                                         \
                mma16816(acc[mi][ni], ah[mi],                                      \
                         bh[ni >> 1][(ni & 1) * 2], bh[ni >> 1][(ni & 1) * 2 + 1]);\
        _Pragma("unroll")                                                          \
        for (int mi = 0; mi < 4; mi++)                                             \
            _Pragma("unroll")                                                      \
            for (int ni = 0; ni < 4; ni++)                                         \
                mma16816(acc[mi][ni], ah[mi],                                      \
                         bl[ni >> 1][(ni & 1) * 2], bl[ni >> 1][(ni & 1) * 2 + 1]);\
    };

// ---- full GEMM; SILU=false: fp32 C=AB+bias; SILU=true: interleaved silu(g)*u -> f16 ----
template <bool SILU>
__global__ __launch_bounds__(256, 2)
void gemm_bias(const f16* __restrict__ Ah,
               const f16* __restrict__ Bh, const f16* __restrict__ Bl,
               const float* __restrict__ bias, float* __restrict__ C,
               f16* __restrict__ Uh, int Kp, int N)
{
    extern __shared__ __align__(128) char smem[];
    const uint32_t sbase = smem_u32(smem);
    const int tid = threadIdx.x, lane = tid & 31, wid = tid >> 5;
    const int warp_m = wid >> 2, warp_n = wid & 3;
    const int row0 = blockIdx.x * 128, col0 = blockIdx.y * 128;

    GEMM_BODY_COMMON

    GEMM_MAINLOOP(0, kc)

    const int g = lane >> 2, tig = lane & 3;
#pragma unroll
    for (int mi = 0; mi < 4; mi++)
#pragma unroll
        for (int half = 0; half < 2; half++) {
            const int r = row0 + warp_m * 64 + mi * 16 + g + half * 8;
#pragma unroll
            for (int ni = 0; ni < 4; ni++) {
                const int col = col0 + warp_n * 32 + ni * 8 + tig * 2;
                const float2 bb = *(const float2*)(bias + col);
                const float v0 = acc[mi][ni][half * 2 + 0] + bb.x;
                const float v1 = acc[mi][ni][half * 2 + 1] + bb.y;
                if (SILU) {
                    const float rr = (v0 / (1.f + __expf(-v0))) * v1;
                    Uh[(size_t)r * FF_PAD + (col >> 1)] = __float2half(rr);
                } else {
                    *(float2*)(C + (size_t)r * N + col) = make_float2(v0, v1);
                }
            }
        }
}

// ---- split-K GEMM: writes raw partials (grid.z = split index) ----
__global__ __launch_bounds__(256, 2)
void gemm_part(const f16* __restrict__ Ah,
               const f16* __restrict__ Bh, const f16* __restrict__ Bl,
               float* __restrict__ part, size_t pstride,
               int Kp, int N)
{
    extern __shared__ __align__(128) char smem[];
    const uint32_t sbase = smem_u32(smem);
    const int tid = threadIdx.x, lane = tid & 31, wid = tid >> 5;
    const int warp_m = wid >> 2, warp_n = wid & 3;
    const int row0 = blockIdx.x * 128, col0 = blockIdx.y * 128;
    const int S = gridDim.z, sidx = blockIdx.z;

    GEMM_BODY_COMMON

    const int npair = kc >> 1;
    const int c0 = 2 * ((sidx * npair) / S);
    const int c1 = 2 * (((sidx + 1) * npair) / S);

    GEMM_MAINLOOP(c0, c1)

    float* P = part + (size_t)sidx * pstride;
    const int g = lane >> 2, tig = lane & 3;
#pragma unroll
    for (int mi = 0; mi < 4; mi++)
#pragma unroll
        for (int half = 0; half < 2; half++) {
            const int r = row0 + warp_m * 64 + mi * 16 + g + half * 8;
#pragma unroll
            for (int ni = 0; ni < 4; ni++) {
                const int col = col0 + warp_n * 32 + ni * 8 + tig * 2;
                *(float2*)(P + (size_t)r * N + col) =
                    make_float2(acc[mi][ni][half * 2 + 0], acc[mi][ni][half * 2 + 1]);
            }
        }
}

// ---------------- fused split-K reduce (+bias,+residual) + rmsnorm -> f16 ----------------
template <bool RES>
__global__ void reduce_rms(const float* __restrict__ part, size_t ps, int S,
                           const float* __restrict__ bias, const float* __restrict__ scale,
                           float* __restrict__ h, f16* __restrict__ yh)
{
    const int row = blockIdx.x;
    const size_t rb = (size_t)row * D_MODEL;
    float v[5];
    float sumsq = 0.f;
#pragma unroll
    for (int j = 0; j < 5; j++) {
        const int i = threadIdx.x + j * 256;
        float val = part[rb + i];
        for (int s = 1; s < S; s++) val += part[(size_t)s * ps + rb + i];
        if (RES) val += bias[i] + h[rb + i];
        h[rb + i] = val;
        v[j] = val;
        sumsq += val * val;
    }
#pragma unroll
    for (int o = 16; o; o >>= 1) sumsq += __shfl_xor_sync(~0u, sumsq, o);
    __shared__ float red[8];
    const int warp = threadIdx.x >> 5, lane = threadIdx.x & 31;
    if (lane == 0) red[warp] = sumsq;
    __syncthreads();
    if (warp == 0) {
        float t = (lane < 8) ? red[lane] : 0.f;
#pragma unroll
        for (int o = 4; o; o >>= 1) t += __shfl_xor_sync(~0u, t, o);
        if (lane == 0) red[0] = t;
    }
    __syncthreads();
    const float rinv = rsqrtf(red[0] * (1.f / D_MODEL) + EPS_RMS);
#pragma unroll
    for (int j = 0; j < 5; j++) {
        const int i = threadIdx.x + j * 256;
        yh[rb + i] = __float2half(v[j] * scale[i] * rinv);
    }
}

// ---------------- fc1 reduce: +bias, gelu -> f16 ----------------
__global__ void reduce_gelu(const float* __restrict__ part, size_t ps, int S,
                            const float* __restrict__ bias,
                            f16* __restrict__ oh, int n4, int N) {
    int i = blockIdx.x * 256 + threadIdx.x;
    if (i >= n4) return;
    const size_t b = (size_t)i * 4;
    float4 a = *(const float4*)(part + b);
    for (int s = 1; s < S; s++) {
        const float4 p = *(const float4*)(part + (size_t)s * ps + b);
        a.x += p.x; a.y += p.y; a.z += p.z; a.w += p.w;
    }
    const float4 bb = *(const float4*)(bias + (int)(b % N));
    float v[4] = { a.x + bb.x, a.y + bb.y, a.z + bb.z, a.w + bb.w };
#pragma unroll
    for (int j = 0; j < 4; j++)
        v[j] = 0.5f * v[j] * (1.f + erff(v[j] * 0.7071067811865475f));
    *(__half2*)(oh + b)     = __floats2half2_rn(v[0], v[1]);
    *(__half2*)(oh + b + 2) = __floats2half2_rn(v[2], v[3]);
}

// ---------------- fc2 reduce: +bias, fp32 out ----------------
__global__ void reduce_bias_out(const float* __restrict__ part, size_t ps, int S,
                                const float* __restrict__ bias, float* __restrict__ out,
                                int n4, int N) {
    int i = blockIdx.x * 256 + threadIdx.x;
    if (i >= n4) return;
    const size_t b = (size_t)i * 4;
    float4 a = *(const float4*)(part + b);
    for (int s = 1; s < S; s++) {
        const float4 p = *(const float4*)(part + (size_t)s * ps + b);
        a.x += p.x; a.y += p.y; a.z += p.z; a.w += p.w;
    }
    const float4 bb = *(const float4*)(bias + (int)(b % N));
    a.x += bb.x; a.y += bb.y; a.z += bb.z; a.w += bb.w;
    *(float4*)(out + b) = a;
}

// ---------------- attention: fused qkv split-K reduce + bias + RoPE -> f16 ----------------
#define ATT_SMEM ((64 * 80 + 64 * 81 + 64 * 80 + 8 * 64) * 4)

__global__ void attn_kernel(const float* __restrict__ part, size_t ps, int S,
                            const float* __restrict__ qkvb,
                            const float* __restrict__ rot,
                            f16* __restrict__ oh)
{
    extern __shared__ float sm[];
    float* qs = sm;
    float* ks = qs + 64 * 80;
    float* vs = ks + 64 * 81;
    float* pr = vs + 64 * 80;
    const int w = blockIdx.x, hh = blockIdx.y;
    const int tid = threadIdx.x, lane = tid & 31, warp = tid >> 5;
    const size_t base = (size_t)w * WIN * (3 * D_MODEL) + hh * HD;
    const int cb = hh * HD;

    for (int idx = tid; idx < WIN * HALF; idx += 256) {
        const int t = idx / HALF, d = idx % HALF;
        float s, c;
        sincosf(rot[(w * WIN + t) * HALF + d], &s, &c);
        const size_t g = base + (size_t)t * (3 * D_MODEL) + d;
        float qre = qkvb[cb + d],           qim = qkvb[cb + d + HALF];
        float kre = qkvb[cb + d + D_MODEL], kim = qkvb[cb + d + D_MODEL + HALF];
        for (int sp = 0; sp < S; sp++) {
            const size_t o = (size_t)sp * ps + g;
            qre += part[o];            qim += part[o + HALF];
            kre += part[o + D_MODEL];  kim += part[o + D_MODEL + HALF];
        }
        qs[t * 80 + d]        = qre * c - qim * s;
        qs[t * 80 + d + HALF] = qre * s + qim * c;
        ks[t * 81 + d]        = kre * c - kim * s;
        ks[t * 81 + d + HALF] = kre * s + kim * c;
    }
    for (int idx = tid; idx < WIN * HD; idx += 256) {
        const int t = idx / HD, d = idx % HD;
        const size_t g = base + (size_t)t * (3 * D_MODEL) + 2 * D_MODEL + d;
        float v = qkvb[cb + d + 2 * D_MODEL];
        for (int sp = 0; sp < S; sp++) v += part[(size_t)sp * ps + g];
        vs[t * 80 + d] = v;
    }
    __syncthreads();

    for (int row = warp; row < WIN; row += 8) {
        const float* qr = qs + row * 80;
        const float* k0 = ks + lane * 81;
        const float* k1 = ks + (lane + 32) * 81;
        float s0 = 0.f, s1 = 0.f;
#pragma unroll
        for (int d = 0; d < HD; d++) { const float q = qr[d]; s0 += q * k0[d]; s1 += q * k1[d]; }
        s0 *= ATT_SCALE; s1 *= ATT_SCALE;
        float mx = fmaxf(s0, s1);
#pragma unroll
        for (int o = 16; o; o >>= 1) mx = fmaxf(mx, __shfl_xor_sync(~0u, mx, o));
        const float e0 = __expf(s0 - mx), e1 = __expf(s1 - mx);
        float sum = e0 + e1;
#pragma unroll
        for (int o = 16; o; o >>= 1) sum += __shfl_xor_sync(~0u, sum, o);
        const float inv = 1.f / sum;
        pr[warp * 64 + lane] = e0 * inv;
        pr[warp * 64 + lane + 32] = e1 * inv;
        __syncwarp();
        float o0 = 0.f, o1 = 0.f, o2 = 0.f;
#pragma unroll 4
        for (int j = 0; j < WIN; j++) {
            const float p = pr[warp * 64 + j];
            const float* vr = vs + j * 80;
            o0 += p * vr[lane];
            o1 += p * vr[lane + 32];
            if (lane < 16) o2 += p * vr[lane + 64];
        }
        const size_t ob = (size_t)(w * WIN + row) * D_MODEL + hh * HD;
        oh[ob + lane]      = __float2half(o0);
        oh[ob + lane + 32] = __float2half(o1);
        if (lane < 16) oh[ob + lane + 64] = __float2half(o2);
        __syncwarp();
    }
}

// ---------------- host ----------------
extern "C" void kernel_launch(void* const* d_in, const int* in_sizes, int n_in,
                              void* d_out, int out_size)
{
    const float* x      = (const float*)d_in[0];
    const float* rot    = (const float*)d_in[1];
    const float* patchw = (const float*)d_in[3];
    const float* qkvw   = (const float*)d_in[4];
    const float* qkvb   = (const float*)d_in[5];
    const float* projw  = (const float*)d_in[6];
    const float* projb  = (const float*)d_in[7];
    const float* n1s    = (const float*)d_in[8];
    const float* n2s    = (const float*)d_in[9];
    const float* gw     = (const float*)d_in[10];
    const float* gb     = (const float*)d_in[11];
    const float* uw     = (const float*)d_in[12];
    const float* ub     = (const float*)d_in[13];
    const float* dw     = (const float*)d_in[14];
    const float* db     = (const float*)d_in[15];
    const float* lnq    = (const float*)d_in[16];
    const float* f1w    = (const float*)d_in[17];
    const float* f1b    = (const float*)d_in[18];
    const float* f2w    = (const float*)d_in[19];
    const float* f2b    = (const float*)d_in[20];
    float* out = (float*)d_out;

    float *h, *gub, *part;
    f16 *xh, *nh, *ath, *uph, *f1h;
    f16 *patchTh, *patchTl, *qkvTh, *qkvTl, *projTh, *projTl;
    f16 *guTh, *guTl, *downTh, *downTl, *fc1Th, *fc1Tl, *fc2Th, *fc2Tl;
#define GA(p, s) cudaGetSymbolAddress((void**)&p, s)
    GA(h, g_h); GA(gub, g_gub); GA(part, g_part);
    GA(xh, g_xh); GA(nh, g_nh); GA(ath, g_ath); GA(uph, g_uph); GA(f1h, g_f1h);
    GA(patchTh, g_patchTh); GA(patchTl, g_patchTl);
    GA(qkvTh, g_qkvTh); GA(qkvTl, g_qkvTl);
    GA(projTh, g_projTh); GA(projTl, g_projTl);
    GA(guTh, g_guTh); GA(guTl, g_guTl);
    GA(downTh, g_downTh); GA(downTl, g_downTl);
    GA(fc1Th, g_fc1Th); GA(fc1Tl, g_fc1Tl);
    GA(fc2Th, g_fc2Th); GA(fc2Tl, g_fc2Tl);
#undef GA

    cudaFuncSetAttribute(attn_kernel, cudaFuncAttributeMaxDynamicSharedMemorySize, ATT_SMEM);
    cudaFuncSetAttribute(gemm_bias<false>, cudaFuncAttributeMaxDynamicSharedMemorySize, GEMM_SMEM);
    cudaFuncSetAttribute(gemm_bias<true>,  cudaFuncAttributeMaxDynamicSharedMemorySize, GEMM_SMEM);
    cudaFuncSetAttribute(gemm_part, cudaFuncAttributeMaxDynamicSharedMemorySize, GEMM_SMEM);

    // ---- setup: activation convert + weight conversion ----
    conv_act<<<(T_TOK * PATCH_KP + 255) / 256, 256>>>(x, xh, T_TOK, PATCH_IN, PATCH_KP);
    build_gub<<<(DEPTH * FF2 + 255) / 256, 256>>>(gb, ub);
    {
        ConvTable tb;
        int tc = 0, si = 0;
        auto add = [&](const float* s, f16* dh, f16* dl, int K, int N, int Kp, int Np,
                       int rstride, int roff) {
            const int tx = (Kp + 31) / 32, ty = (Np + 31) / 32;
            tb.seg[si] = { s, dh, dl, K, N, Kp, tc, tx, rstride, roff };
            tc += tx * ty; si++;
        };
        add(patchw, patchTh, patchTl, PATCH_IN, 1280, PATCH_KP, 1280, 1, 0);
        for (int l = 0; l < DEPTH; l++) {
            add(qkvw + (size_t)l * 1280 * 3840, qkvTh + (size_t)l * 3840 * 1280,
                qkvTl + (size_t)l * 3840 * 1280, 1280, 3840, 1280, 3840, 1, 0);
            add(projw + (size_t)l * 1280 * 1280, projTh + (size_t)l * 1280 * 1280,
                projTl + (size_t)l * 1280 * 1280, 1280, 1280, 1280, 1280, 1, 0);
            add(gw + (size_t)l * 1280 * FF_DIM, guTh + (size_t)l * FF2 * 1280,
                guTl + (size_t)l * FF2 * 1280, 1280, FF_DIM, 1280, FF_PAD, 2, 0);
            add(uw + (size_t)l * 1280 * FF_DIM, guTh + (size_t)l * FF2 * 1280,
                guTl + (size_t)l * FF2 * 1280, 1280, FF_DIM, 1280, FF_PAD, 2, 1);
            add(dw + (size_t)l * FF_DIM * 1280, downTh + (size_t)l * 1280 * FF_PAD,
                downTl + (size_t)l * 1280 * FF_PAD, FF_DIM, 1280, FF_PAD, 1280, 1, 0);
        }
        add(f1w, fc1Th, fc1Tl, 5120, 5120, 5120, 5120, 1, 0);
        add(f2w, fc2Th, fc2Tl, 5120, 3584, 5120, 3584, 1, 0);
        conv_all<<<tc, dim3(32, 8)>>>(tb);
    }

    const size_t psD  = (size_t)T_TOK * D_MODEL;
    const size_t psQ  = (size_t)T_TOK * 3 * D_MODEL;
    const size_t psF  = (size_t)512 * 5120;
    const size_t psF2 = (size_t)512 * OUT_DIM;
    const int n4F  = 512 * 5120 / 4;
    const int n4F2 = 512 * OUT_DIM / 4;

    // ---- patch embed: split-K5 + fused reduce/rmsnorm(n1 layer0) ----
    gemm_part<<<dim3(16, 10, 5), 256, GEMM_SMEM>>>(
        xh, patchTh, patchTl, part, psD, PATCH_KP, 1280);
    reduce_rms<false><<<T_TOK, 256>>>(part, psD, 5, nullptr, n1s, h, nh);

    for (int l = 0; l < DEPTH; l++) {
        const size_t lD = (size_t)l * D_MODEL;
        // qkv: split-K3; reduction fused into attention
        gemm_part<<<dim3(16, 30, 3), 256, GEMM_SMEM>>>(
            nh, qkvTh + (size_t)l * 3840 * 1280, qkvTl + (size_t)l * 3840 * 1280,
            part, psQ, 1280, 3840);
        attn_kernel<<<dim3(NWIN, H_HEADS), 256, ATT_SMEM>>>(
            part, psQ, 3, qkvb + (size_t)l * 3840, rot, ath);
        // proj: split-K5, then fused reduce+res+rmsnorm(n2)
        gemm_part<<<dim3(16, 10, 5), 256, GEMM_SMEM>>>(
            ath, projTh + (size_t)l * 1280 * 1280, projTl + (size_t)l * 1280 * 1280,
            part, psD, 1280, 1280);
        reduce_rms<true><<<T_TOK, 256>>>(part, psD, 5, projb + lD, n2s + lD, h, nh);
        // fused gate|up GEMM with silu epilogue (interleaved cols)
        gemm_bias<true><<<dim3(16, FF2 / 128), 256, GEMM_SMEM>>>(
            nh, guTh + (size_t)l * FF2 * 1280, guTl + (size_t)l * FF2 * 1280,
            gub + (size_t)l * FF2, nullptr, uph, 1280, FF2);
        // down: split-K5, then fused reduce+res+rmsnorm(next n1 or lnq)
        gemm_part<<<dim3(16, 10, 5), 256, GEMM_SMEM>>>(
            uph, downTh + (size_t)l * 1280 * FF_PAD, downTl + (size_t)l * 1280 * FF_PAD,
            part, psD, FF_PAD, 1280);
        const float* nexts = (l < DEPTH - 1) ? (n1s + (size_t)(l + 1) * D_MODEL) : lnq;
        reduce_rms<true><<<T_TOK, 256>>>(part, psD, 5, db + lD, nexts, h, nh);
    }

    // ---- merger (nh viewed as [512, 5120]) ----
    gemm_part<<<dim3(4, 40, 8), 256, GEMM_SMEM>>>(
        nh, fc1Th, fc1Tl, part, psF, 5120, 5120);
    reduce_gelu<<<(n4F + 255) / 256, 256>>>(part, psF, 8, f1b, f1h, n4F, 5120);
    // fc2: split-K4 + bias reduce to output
    gemm_part<<<dim3(4, 28, 4), 256, GEMM_SMEM>>>(
        f1h, fc2Th, fc2Tl, part, psF2, 5120, OUT_DIM);
    reduce_bias_out<<<(n4F2 + 255) / 256, 256>>>(part, psF2, 4, f2b, out, n4F2, OUT_DIM);
}

// round 17
// speedup vs baseline: 2.7094x; 1.3494x over previous
#include <cuda_runtime.h>
#include <cuda_fp16.h>
#include <math.h>
#include <stdint.h>

// ---------------- problem constants ----------------
#define T_TOK   2048
#define D_MODEL 1280
#define H_HEADS 16
#define HD      80
#define HALF    40
#define FF_DIM  3420
#define FF_PAD  3456
#define FF2     (2 * FF_PAD)          // 6912 interleaved gate|up
#define DEPTH   4
#define OUT_DIM 3584
#define PATCH_IN 1176
#define PATCH_KP 1216
#define WIN     64
#define NWIN    (T_TOK / WIN)
#define EPS_RMS 1e-6f
#define ATT_SCALE 0.1118033988749895f

typedef __half f16;

// ---------------- helpers ----------------
__device__ __forceinline__ uint32_t smem_u32(const void* p) {
    uint32_t a;
    asm("{ .reg .u64 t; cvta.to.shared.u64 t, %1; cvt.u32.u64 %0, t; }" : "=r"(a) : "l"(p));
    return a;
}
__device__ __forceinline__ void cp_async16(uint32_t s, const void* g) {
    asm volatile("cp.async.cg.shared.global [%0], [%1], 16;" :: "r"(s), "l"(g));
}
#define CP_COMMIT() asm volatile("cp.async.commit_group;" ::: "memory")
#define CP_WAIT(n)  asm volatile("cp.async.wait_group %0;" :: "n"(n) : "memory")

__device__ __forceinline__ void ldm_x4(uint32_t& r0, uint32_t& r1, uint32_t& r2,
                                       uint32_t& r3, uint32_t addr) {
    asm volatile("ldmatrix.sync.aligned.m8n8.x4.shared.b16 {%0,%1,%2,%3}, [%4];"
                 : "=r"(r0), "=r"(r1), "=r"(r2), "=r"(r3) : "r"(addr));
}
__device__ __forceinline__ void mma16816(float* d, const uint32_t* a,
                                         uint32_t b0, uint32_t b1) {
    asm volatile("mma.sync.aligned.m16n8k16.row.col.f32.f16.f16.f32 "
                 "{%0,%1,%2,%3}, {%4,%5,%6,%7}, {%8,%9}, {%0,%1,%2,%3};"
                 : "+f"(d[0]), "+f"(d[1]), "+f"(d[2]), "+f"(d[3])
                 : "r"(a[0]), "r"(a[1]), "r"(a[2]), "r"(a[3]), "r"(b0), "r"(b1));
}
// swizzled smem byte offset for 32B rows (two 16B segs), conflict-free for ldmatrix
__device__ __forceinline__ uint32_t swz16(int row, int seg) {
    return (uint32_t)(row * 32 + ((seg ^ ((row >> 2) & 1)) << 4));
}

// ---------------- scratch ----------------
__device__ float g_h  [T_TOK * D_MODEL];
__device__ float g_gub[DEPTH * FF2];
__device__ float g_part[(size_t)3 * T_TOK * 3 * D_MODEL];
__device__ f16  g_xh [T_TOK * PATCH_KP];
__device__ f16  g_nh [T_TOK * D_MODEL];
__device__ f16  g_ath[T_TOK * D_MODEL];
__device__ f16  g_uph[(size_t)T_TOK * FF_PAD];
__device__ f16  g_f1h[512 * 4 * D_MODEL];
// transposed weights [N, Kp] (single fp16 plane)
__device__ f16 g_patchT[1280 * PATCH_KP];
__device__ f16 g_qkvT [DEPTH * 3840 * 1280];
__device__ f16 g_projT[DEPTH * 1280 * 1280];
__device__ f16 g_guT  [(size_t)DEPTH * FF2 * 1280];
__device__ f16 g_downT[(size_t)DEPTH * 1280 * FF_PAD];
__device__ f16 g_fc1T [5120 * 5120];
__device__ f16 g_fc2T [3584 * 5120];

// ---------------- activation convert (single fp16 plane) ----------------
__global__ void conv_act(const float* __restrict__ X, f16* __restrict__ Xh,
                         int M, int K, int Kp) {
    int idx = blockIdx.x * 256 + threadIdx.x;
    if (idx >= M * Kp) return;
    int m = idx / Kp, k = idx - m * Kp;
    float v = (k < K) ? X[(size_t)m * K + k] : 0.f;
    Xh[idx] = __float2half(v);
}

// ---------------- interleaved gate|up bias builder ----------------
__global__ void build_gub(const float* __restrict__ gb, const float* __restrict__ ub) {
    int idx = blockIdx.x * 256 + threadIdx.x;
    if (idx >= DEPTH * FF2) return;
    const int l = idx / FF2, c = idx - l * FF2;
    const int f = c >> 1;
    float v = 0.f;
    if (f < FF_DIM) v = (c & 1) ? ub[l * FF_DIM + f] : gb[l * FF_DIM + f];
    g_gub[idx] = v;
}

// ---------------- batched weight transpose (single fp16 plane) ----------------
#define NSEG 23
struct Seg { const float* s; f16* dh; int K, N, Kp, tile0, tilesX, rstride, roff; };
struct ConvTable { Seg seg[NSEG]; };

__global__ void conv_all(ConvTable tb) {
    __shared__ float t[32][33];
    const int tile = blockIdx.x;
    int si = 0;
#pragma unroll
    for (int i = 1; i < NSEG; i++) si += (tb.seg[i].tile0 <= tile);
    const Seg sg = tb.seg[si];
    const int lt = tile - sg.tile0;
    const int kb = (lt % sg.tilesX) * 32;
    const int nb = (lt / sg.tilesX) * 32;
#pragma unroll
    for (int j = 0; j < 32; j += 8) {
        int k = kb + threadIdx.y + j, n = nb + threadIdx.x;
        t[threadIdx.y + j][threadIdx.x] =
            (k < sg.K && n < sg.N) ? sg.s[(size_t)k * sg.N + n] : 0.f;
    }
    __syncthreads();
#pragma unroll
    for (int j = 0; j < 32; j += 8) {
        int n = nb + threadIdx.y + j, k = kb + threadIdx.x;
        if (k < sg.Kp) {
            const size_t dr = (size_t)n * sg.rstride + sg.roff;
            sg.dh[dr * sg.Kp + k] = __float2half(t[threadIdx.x][threadIdx.y + j]);
        }
    }
}

// ---------------- GEMM: single-pass fp16, k16 chunks, quad mainloop, occ 2 ----------------
#define NSTAGE 12
#define STAGE_BYTES (2 * 128 * 32)            // 8192: Ah | Bh
#define GEMM_SMEM (NSTAGE * STAGE_BYTES)      // 98304 -> 2 CTAs/SM

#define GEMM_MAINLOOP(C0, C1)                                                      \
    _Pragma("unroll")                                                              \
    for (int i = 0; i < 8; i++) loadChunk((C0) + i, i);                            \
    for (int c = (C0); c < (C1); c += 4) {                                         \
        if (c + 4 < (C1)) { CP_WAIT(4); } else { CP_WAIT(0); }                     \
        __syncthreads();                                                           \
        _Pragma("unroll")                                                          \
        for (int j = 0; j < 4; j++)                                                \
            if (c + 8 + j < (C1)) loadChunk(c + 8 + j, (c + 8 + j - (C0)) % NSTAGE); \
        computeChunk((c + 0 - (C0)) % NSTAGE);                                     \
        computeChunk((c + 1 - (C0)) % NSTAGE);                                     \
        computeChunk((c + 2 - (C0)) % NSTAGE);                                     \
        computeChunk((c + 3 - (C0)) % NSTAGE);                                     \
    }

#define GEMM_BODY_COMMON                                                           \
    const int kc = Kp >> 4;            /* k16 chunks */                            \
    const size_t rowB = (size_t)Kp * 2;                                            \
    const int ld_r = tid >> 1;                                                     \
    const int ld_s = tid & 1;                                                      \
    auto loadChunk = [&](int c, int buf) {                                         \
        const size_t kk = (size_t)c * 32;                                          \
        const size_t go = (size_t)ld_r * rowB + kk + ld_s * 16;                    \
        const uint32_t so = swz16(ld_r, ld_s);                                     \
        const uint32_t sA = sbase + buf * STAGE_BYTES;                             \
        cp_async16(sA + so,        (const char*)Ah + (size_t)row0 * rowB + go);    \
        cp_async16(sA + 4096 + so, (const char*)Bh + (size_t)col0 * rowB + go);    \
        CP_COMMIT();                                                               \
    };                                                                             \
    float acc[4][4][4];                                                            \
    _Pragma("unroll")                                                              \
    for (int i = 0; i < 4; i++)                                                    \
        _Pragma("unroll")                                                          \
        for (int j = 0; j < 4; j++)                                                \
            _Pragma("unroll")                                                      \
            for (int q = 0; q < 4; q++) acc[i][j][q] = 0.f;                        \
    const int a_row = warp_m * 64 + (lane & 15);                                   \
    const int a_seg = (lane >> 4);                                                 \
    const int b_row = warp_n * 32 + (lane & 7) + ((lane >> 4) << 3);               \
    const int b_seg = (lane >> 3) & 1;                                             \
    auto computeChunk = [&](int buf) {                                             \
        const uint32_t sA = sbase + buf * STAGE_BYTES;                             \
        const uint32_t sB = sA + 4096;                                             \
        uint32_t ah[4][4], bh[2][4];                                               \
        _Pragma("unroll")                                                          \
        for (int mi = 0; mi < 4; mi++)                                             \
            ldm_x4(ah[mi][0], ah[mi][1], ah[mi][2], ah[mi][3],                     \
                   sA + swz16(a_row + mi * 16, a_seg));                            \
        _Pragma("unroll")                                                          \
        for (int j = 0; j < 2; j++)                                                \
            ldm_x4(bh[j][0], bh[j][1], bh[j][2], bh[j][3],                         \
                   sB + swz16(b_row + j * 16, b_seg));                             \
        _Pragma("unroll")                                                          \
        for (int mi = 0; mi < 4; mi++)                                             \
            _Pragma("unroll")                                                      \
            for (int ni = 0; ni < 4; ni++)                                         \
                mma16816(acc[mi][ni], ah[mi],                                      \
                         bh[ni >> 1][(ni & 1) * 2], bh[ni >> 1][(ni & 1) * 2 + 1]);\
    };

// ---- full GEMM; SILU=false: fp32 C=AB+bias; SILU=true: interleaved silu(g)*u -> f16 ----
template <bool SILU>
__global__ __launch_bounds__(256, 2)
void gemm_bias(const f16* __restrict__ Ah, const f16* __restrict__ Bh,
               const float* __restrict__ bias, float* __restrict__ C,
               f16* __restrict__ Uh, int Kp, int N)
{
    extern __shared__ __align__(128) char smem[];
    const uint32_t sbase = smem_u32(smem);
    const int tid = threadIdx.x, lane = tid & 31, wid = tid >> 5;
    const int warp_m = wid >> 2, warp_n = wid & 3;
    const int row0 = blockIdx.x * 128, col0 = blockIdx.y * 128;

    GEMM_BODY_COMMON

    GEMM_MAINLOOP(0, kc)

    const int g = lane >> 2, tig = lane & 3;
#pragma unroll
    for (int mi = 0; mi < 4; mi++)
#pragma unroll
        for (int half = 0; half < 2; half++) {
            const int r = row0 + warp_m * 64 + mi * 16 + g + half * 8;
#pragma unroll
            for (int ni = 0; ni < 4; ni++) {
                const int col = col0 + warp_n * 32 + ni * 8 + tig * 2;
                const float2 bb = *(const float2*)(bias + col);
                const float v0 = acc[mi][ni][half * 2 + 0] + bb.x;
                const float v1 = acc[mi][ni][half * 2 + 1] + bb.y;
                if (SILU) {
                    const float rr = (v0 / (1.f + __expf(-v0))) * v1;
                    Uh[(size_t)r * FF_PAD + (col >> 1)] = __float2half(rr);
                } else {
                    *(float2*)(C + (size_t)r * N + col) = make_float2(v0, v1);
                }
            }
        }
}

// ---- split-K GEMM: writes raw partials (grid.z = split index; quad-aligned segments) ----
__global__ __launch_bounds__(256, 2)
void gemm_part(const f16* __restrict__ Ah, const f16* __restrict__ Bh,
               float* __restrict__ part, size_t pstride,
               int Kp, int N)
{
    extern __shared__ __align__(128) char smem[];
    const uint32_t sbase = smem_u32(smem);
    const int tid = threadIdx.x, lane = tid & 31, wid = tid >> 5;
    const int warp_m = wid >> 2, warp_n = wid & 3;
    const int row0 = blockIdx.x * 128, col0 = blockIdx.y * 128;
    const int S = gridDim.z, sidx = blockIdx.z;

    GEMM_BODY_COMMON

    const int nquad = kc >> 2;
    const int c0 = 4 * ((sidx * nquad) / S);
    const int c1 = 4 * (((sidx + 1) * nquad) / S);

    GEMM_MAINLOOP(c0, c1)

    float* P = part + (size_t)sidx * pstride;
    const int g = lane >> 2, tig = lane & 3;
#pragma unroll
    for (int mi = 0; mi < 4; mi++)
#pragma unroll
        for (int half = 0; half < 2; half++) {
            const int r = row0 + warp_m * 64 + mi * 16 + g + half * 8;
#pragma unroll
            for (int ni = 0; ni < 4; ni++) {
                const int col = col0 + warp_n * 32 + ni * 8 + tig * 2;
                *(float2*)(P + (size_t)r * N + col) =
                    make_float2(acc[mi][ni][half * 2 + 0], acc[mi][ni][half * 2 + 1]);
            }
        }
}

// ---------------- fused split-K reduce (+bias,+residual) + rmsnorm -> f16 ----------------
template <bool RES>
__global__ void reduce_rms(const float* __restrict__ part, size_t ps, int S,
                           const float* __restrict__ bias, const float* __restrict__ scale,
                           float* __restrict__ h, f16* __restrict__ yh)
{
    const int row = blockIdx.x;
    const size_t rb = (size_t)row * D_MODEL;
    float v[5];
    float sumsq = 0.f;
#pragma unroll
    for (int j = 0; j < 5; j++) {
        const int i = threadIdx.x + j * 256;
        float val = part[rb + i];
        for (int s = 1; s < S; s++) val += part[(size_t)s * ps + rb + i];
        if (RES) val += bias[i] + h[rb + i];
        h[rb + i] = val;
        v[j] = val;
        sumsq += val * val;
    }
#pragma unroll
    for (int o = 16; o; o >>= 1) sumsq += __shfl_xor_sync(~0u, sumsq, o);
    __shared__ float red[8];
    const int warp = threadIdx.x >> 5, lane = threadIdx.x & 31;
    if (lane == 0) red[warp] = sumsq;
    __syncthreads();
    if (warp == 0) {
        float t = (lane < 8) ? red[lane] : 0.f;
#pragma unroll
        for (int o = 4; o; o >>= 1) t += __shfl_xor_sync(~0u, t, o);
        if (lane == 0) red[0] = t;
    }
    __syncthreads();
    const float rinv = rsqrtf(red[0] * (1.f / D_MODEL) + EPS_RMS);
#pragma unroll
    for (int j = 0; j < 5; j++) {
        const int i = threadIdx.x + j * 256;
        yh[rb + i] = __float2half(v[j] * scale[i] * rinv);
    }
}

// ---------------- fc1 reduce: +bias, gelu -> f16 ----------------
__global__ void reduce_gelu(const float* __restrict__ part, size_t ps, int S,
                            const float* __restrict__ bias,
                            f16* __restrict__ oh, int n4, int N) {
    int i = blockIdx.x * 256 + threadIdx.x;
    if (i >= n4) return;
    const size_t b = (size_t)i * 4;
    float4 a = *(const float4*)(part + b);
    for (int s = 1; s < S; s++) {
        const float4 p = *(const float4*)(part + (size_t)s * ps + b);
        a.x += p.x; a.y += p.y; a.z += p.z; a.w += p.w;
    }
    const float4 bb = *(const float4*)(bias + (int)(b % N));
    float v[4] = { a.x + bb.x, a.y + bb.y, a.z + bb.z, a.w + bb.w };
#pragma unroll
    for (int j = 0; j < 4; j++)
        v[j] = 0.5f * v[j] * (1.f + erff(v[j] * 0.7071067811865475f));
    *(__half2*)(oh + b)     = __floats2half2_rn(v[0], v[1]);
    *(__half2*)(oh + b + 2) = __floats2half2_rn(v[2], v[3]);
}

// ---------------- fc2 reduce: +bias, fp32 out ----------------
__global__ void reduce_bias_out(const float* __restrict__ part, size_t ps, int S,
                                const float* __restrict__ bias, float* __restrict__ out,
                                int n4, int N) {
    int i = blockIdx.x * 256 + threadIdx.x;
    if (i >= n4) return;
    const size_t b = (size_t)i * 4;
    float4 a = *(const float4*)(part + b);
    for (int s = 1; s < S; s++) {
        const float4 p = *(const float4*)(part + (size_t)s * ps + b);
        a.x += p.x; a.y += p.y; a.z += p.z; a.w += p.w;
    }
    const float4 bb = *(const float4*)(bias + (int)(b % N));
    a.x += bb.x; a.y += bb.y; a.z += bb.z; a.w += bb.w;
    *(float4*)(out + b) = a;
}

// ---------------- attention: fused qkv split-K reduce + bias + RoPE -> f16 ----------------
#define ATT_SMEM ((64 * 80 + 64 * 81 + 64 * 80 + 8 * 64) * 4)

__global__ void attn_kernel(const float* __restrict__ part, size_t ps, int S,
                            const float* __restrict__ qkvb,
                            const float* __restrict__ rot,
                            f16* __restrict__ oh)
{
    extern __shared__ float sm[];
    float* qs = sm;
    float* ks = qs + 64 * 80;
    float* vs = ks + 64 * 81;
    float* pr = vs + 64 * 80;
    const int w = blockIdx.x, hh = blockIdx.y;
    const int tid = threadIdx.x, lane = tid & 31, warp = tid >> 5;
    const size_t base = (size_t)w * WIN * (3 * D_MODEL) + hh * HD;
    const int cb = hh * HD;

    for (int idx = tid; idx < WIN * HALF; idx += 256) {
        const int t = idx / HALF, d = idx % HALF;
        float s, c;
        sincosf(rot[(w * WIN + t) * HALF + d], &s, &c);
        const size_t g = base + (size_t)t * (3 * D_MODEL) + d;
        float qre = qkvb[cb + d],           qim = qkvb[cb + d + HALF];
        float kre = qkvb[cb + d + D_MODEL], kim = qkvb[cb + d + D_MODEL + HALF];
        for (int sp = 0; sp < S; sp++) {
            const size_t o = (size_t)sp * ps + g;
            qre += part[o];            qim += part[o + HALF];
            kre += part[o + D_MODEL];  kim += part[o + D_MODEL + HALF];
        }
        qs[t * 80 + d]        = qre * c - qim * s;
        qs[t * 80 + d + HALF] = qre * s + qim * c;
        ks[t * 81 + d]        = kre * c - kim * s;
        ks[t * 81 + d + HALF] = kre * s + kim * c;
    }
    for (int idx = tid; idx < WIN * HD; idx += 256) {
        const int t = idx / HD, d = idx % HD;
        const size_t g = base + (size_t)t * (3 * D_MODEL) + 2 * D_MODEL + d;
        float v = qkvb[cb + d + 2 * D_MODEL];
        for (int sp = 0; sp < S; sp++) v += part[(size_t)sp * ps + g];
        vs[t * 80 + d] = v;
    }
    __syncthreads();

    for (int row = warp; row < WIN; row += 8) {
        const float* qr = qs + row * 80;
        const float* k0 = ks + lane * 81;
        const float* k1 = ks + (lane + 32) * 81;
        float s0 = 0.f, s1 = 0.f;
#pragma unroll
        for (int d = 0; d < HD; d++) { const float q = qr[d]; s0 += q * k0[d]; s1 += q * k1[d]; }
        s0 *= ATT_SCALE; s1 *= ATT_SCALE;
        float mx = fmaxf(s0, s1);
#pragma unroll
        for (int o = 16; o; o >>= 1) mx = fmaxf(mx, __shfl_xor_sync(~0u, mx, o));
        const float e0 = __expf(s0 - mx), e1 = __expf(s1 - mx);
        float sum = e0 + e1;
#pragma unroll
        for (int o = 16; o; o >>= 1) sum += __shfl_xor_sync(~0u, sum, o);
        const float inv = 1.f / sum;
        pr[warp * 64 + lane] = e0 * inv;
        pr[warp * 64 + lane + 32] = e1 * inv;
        __syncwarp();
        float o0 = 0.f, o1 = 0.f, o2 = 0.f;
#pragma unroll 4
        for (int j = 0; j < WIN; j++) {
            const float p = pr[warp * 64 + j];
            const float* vr = vs + j * 80;
            o0 += p * vr[lane];
            o1 += p * vr[lane + 32];
            if (lane < 16) o2 += p * vr[lane + 64];
        }
        const size_t ob = (size_t)(w * WIN + row) * D_MODEL + hh * HD;
        oh[ob + lane]      = __float2half(o0);
        oh[ob + lane + 32] = __float2half(o1);
        if (lane < 16) oh[ob + lane + 64] = __float2half(o2);
        __syncwarp();
    }
}

// ---------------- host ----------------
extern "C" void kernel_launch(void* const* d_in, const int* in_sizes, int n_in,
                              void* d_out, int out_size)
{
    const float* x      = (const float*)d_in[0];
    const float* rot    = (const float*)d_in[1];
    const float* patchw = (const float*)d_in[3];
    const float* qkvw   = (const float*)d_in[4];
    const float* qkvb   = (const float*)d_in[5];
    const float* projw  = (const float*)d_in[6];
    const float* projb  = (const float*)d_in[7];
    const float* n1s    = (const float*)d_in[8];
    const float* n2s    = (const float*)d_in[9];
    const float* gw     = (const float*)d_in[10];
    const float* gb     = (const float*)d_in[11];
    const float* uw     = (const float*)d_in[12];
    const float* ub     = (const float*)d_in[13];
    const float* dw     = (const float*)d_in[14];
    const float* db     = (const float*)d_in[15];
    const float* lnq    = (const float*)d_in[16];
    const float* f1w    = (const float*)d_in[17];
    const float* f1b    = (const float*)d_in[18];
    const float* f2w    = (const float*)d_in[19];
    const float* f2b    = (const float*)d_in[20];
    float* out = (float*)d_out;

    float *h, *gub, *part;
    f16 *xh, *nh, *ath, *uph, *f1h;
    f16 *patchT, *qkvT, *projT, *guT, *downT, *fc1T, *fc2T;
#define GA(p, s) cudaGetSymbolAddress((void**)&p, s)
    GA(h, g_h); GA(gub, g_gub); GA(part, g_part);
    GA(xh, g_xh); GA(nh, g_nh); GA(ath, g_ath); GA(uph, g_uph); GA(f1h, g_f1h);
    GA(patchT, g_patchT); GA(qkvT, g_qkvT); GA(projT, g_projT);
    GA(guT, g_guT); GA(downT, g_downT); GA(fc1T, g_fc1T); GA(fc2T, g_fc2T);
#undef GA

    cudaFuncSetAttribute(attn_kernel, cudaFuncAttributeMaxDynamicSharedMemorySize, ATT_SMEM);
    cudaFuncSetAttribute(gemm_bias<false>, cudaFuncAttributeMaxDynamicSharedMemorySize, GEMM_SMEM);
    cudaFuncSetAttribute(gemm_bias<true>,  cudaFuncAttributeMaxDynamicSharedMemorySize, GEMM_SMEM);
    cudaFuncSetAttribute(gemm_part, cudaFuncAttributeMaxDynamicSharedMemorySize, GEMM_SMEM);

    // ---- setup: activation convert + weight conversion ----
    conv_act<<<(T_TOK * PATCH_KP + 255) / 256, 256>>>(x, xh, T_TOK, PATCH_IN, PATCH_KP);
    build_gub<<<(DEPTH * FF2 + 255) / 256, 256>>>(gb, ub);
    {
        ConvTable tb;
        int tc = 0, si = 0;
        auto add = [&](const float* s, f16* dh, int K, int N, int Kp, int Np,
                       int rstride, int roff) {
            const int tx = (Kp + 31) / 32, ty = (Np + 31) / 32;
            tb.seg[si] = { s, dh, K, N, Kp, tc, tx, rstride, roff };
            tc += tx * ty; si++;
        };
        add(patchw, patchT, PATCH_IN, 1280, PATCH_KP, 1280, 1, 0);
        for (int l = 0; l < DEPTH; l++) {
            add(qkvw + (size_t)l * 1280 * 3840, qkvT + (size_t)l * 3840 * 1280,
                1280, 3840, 1280, 3840, 1, 0);
            add(projw + (size_t)l * 1280 * 1280, projT + (size_t)l * 1280 * 1280,
                1280, 1280, 1280, 1280, 1, 0);
            add(gw + (size_t)l * 1280 * FF_DIM, guT + (size_t)l * FF2 * 1280,
                1280, FF_DIM, 1280, FF_PAD, 2, 0);
            add(uw + (size_t)l * 1280 * FF_DIM, guT + (size_t)l * FF2 * 1280,
                1280, FF_DIM, 1280, FF_PAD, 2, 1);
            add(dw + (size_t)l * FF_DIM * 1280, downT + (size_t)l * 1280 * FF_PAD,
                FF_DIM, 1280, FF_PAD, 1280, 1, 0);
        }
        add(f1w, fc1T, 5120, 5120, 5120, 5120, 1, 0);
        add(f2w, fc2T, 5120, 3584, 5120, 3584, 1, 0);
        conv_all<<<tc, dim3(32, 8)>>>(tb);
    }

    const size_t psD  = (size_t)T_TOK * D_MODEL;
    const size_t psQ  = (size_t)T_TOK * 3 * D_MODEL;
    const size_t psF  = (size_t)512 * 5120;
    const size_t psF2 = (size_t)512 * OUT_DIM;
    const int n4F  = 512 * 5120 / 4;
    const int n4F2 = 512 * OUT_DIM / 4;

    // ---- patch embed: split-K5 + fused reduce/rmsnorm(n1 layer0) ----
    gemm_part<<<dim3(16, 10, 5), 256, GEMM_SMEM>>>(
        xh, patchT, part, psD, PATCH_KP, 1280);
    reduce_rms<false><<<T_TOK, 256>>>(part, psD, 5, nullptr, n1s, h, nh);

    for (int l = 0; l < DEPTH; l++) {
        const size_t lD = (size_t)l * D_MODEL;
        // qkv: split-K3; reduction fused into attention
        gemm_part<<<dim3(16, 30, 3), 256, GEMM_SMEM>>>(
            nh, qkvT + (size_t)l * 3840 * 1280, part, psQ, 1280, 3840);
        attn_kernel<<<dim3(NWIN, H_HEADS), 256, ATT_SMEM>>>(
            part, psQ, 3, qkvb + (size_t)l * 3840, rot, ath);
        // proj: split-K5, then fused reduce+res+rmsnorm(n2)
        gemm_part<<<dim3(16, 10, 5), 256, GEMM_SMEM>>>(
            ath, projT + (size_t)l * 1280 * 1280, part, psD, 1280, 1280);
        reduce_rms<true><<<T_TOK, 256>>>(part, psD, 5, projb + lD, n2s + lD, h, nh);
        // fused gate|up GEMM with silu epilogue (interleaved cols)
        gemm_bias<true><<<dim3(16, FF2 / 128), 256, GEMM_SMEM>>>(
            nh, guT + (size_t)l * FF2 * 1280, gub + (size_t)l * FF2,
            nullptr, uph, 1280, FF2);
        // down: split-K5, then fused reduce+res+rmsnorm(next n1 or lnq)
        gemm_part<<<dim3(16, 10, 5), 256, GEMM_SMEM>>>(
            uph, downT + (size_t)l * 1280 * FF_PAD, part, psD, FF_PAD, 1280);
        const float* nexts = (l < DEPTH - 1) ? (n1s + (size_t)(l + 1) * D_MODEL) : lnq;
        reduce_rms<true><<<T_TOK, 256>>>(part, psD, 5, db + lD, nexts, h, nh);
    }

    // ---- merger (nh viewed as [512, 5120]) ----
    gemm_part<<<dim3(4, 40, 8), 256, GEMM_SMEM>>>(
        nh, fc1T, part, psF, 5120, 5120);
    reduce_gelu<<<(n4F + 255) / 256, 256>>>(part, psF, 8, f1b, f1h, n4F, 5120);
    // fc2: split-K4 + bias reduce to output
    gemm_part<<<dim3(4, 28, 4), 256, GEMM_SMEM>>>(
        f1h, fc2T, part, psF2, 5120, OUT_DIM);
    reduce_bias_out<<<(n4F2 + 255) / 256, 256>>>(part, psF2, 4, f2b, out, n4F2, OUT_DIM);
}